// round 14
// baseline (speedup 1.0000x reference)
#include <cuda_runtime.h>
#include <cuda_fp16.h>
#include <math.h>

// Problem constants
#define BB    8
#define LLEN  384
#define HIDN  512
#define NHEAD 8
#define DHEAD 64
#define PROWS 768
#define NBH   (BB*NHEAD)

// GEMM tile config
#define BM 128
#define BN 64
#define BK 32
#define PAD 40   // smem row stride in halves
#define ASTR 72  // 64-wide tile stride (halves)
#define RSTR 136 // ring row stride (halves)
#define TSTR 136 // V-transpose staging stride (halves)
#define FSTR 72  // final kernel stage stride (halves)
#define OSTR 68  // float O-combine scratch stride (floats)

// ---------------------------------------------------------------------------
// Scratch (device globals)
// ---------------------------------------------------------------------------
__device__ __half g_xk[BB*LLEN*HIDN];
__device__ __half g_xq[BB*LLEN*HIDN];
__device__ __half g_xv[BB*LLEN*HIDN];
__device__ __half g_pe16[PROWS*HIDN];
__device__ __half g_wq16[HIDN*HIDN];
__device__ __half g_wk16[HIDN*HIDN];
__device__ __half g_wv16[HIDN*HIDN];
__device__ __half g_wr16[HIDN*HIDN];
__device__ __half g_wf16[HIDN*HIDN];

__device__ __half g_qu[BB*LLEN*HIDN];
__device__ __half g_qv[BB*LLEN*HIDN];
__device__ __half g_k16[BB*LLEN*HIDN];
__device__ __half g_r16[PROWS*HIDN];
__device__ __half g_vT[NBH*DHEAD*LLEN];
__device__ __half g_ctx16[BB*LLEN*HIDN];

// ---------------------------------------------------------------------------
// fp32 -> fp16 convert (flattened)
// ---------------------------------------------------------------------------
struct CvtArgs {
    const float* src[9];
    __half*      dst[9];
    int          cum[10];
};

__global__ __launch_bounds__(256) void cvt_kernel(CvtArgs a) {
    const int gi = (blockIdx.x * 256 + threadIdx.x) * 8;
    if (gi >= a.cum[9]) return;
    int ti = 0;
#pragma unroll
    for (int k = 1; k < 9; k++) ti += (gi >= a.cum[k]) ? 1 : 0;
    const int off = gi - a.cum[ti];
    const float4* s = (const float4*)(a.src[ti] + off);
    float4 x = s[0], y = s[1];
    __half2 h0 = __floats2half2_rn(x.x, x.y);
    __half2 h1 = __floats2half2_rn(x.z, x.w);
    __half2 h2 = __floats2half2_rn(y.x, y.y);
    __half2 h3 = __floats2half2_rn(y.z, y.w);
    uint4 o;
    o.x = *(unsigned*)&h0; o.y = *(unsigned*)&h1;
    o.z = *(unsigned*)&h2; o.w = *(unsigned*)&h3;
    *(uint4*)(a.dst[ti] + off) = o;
}

// ---------------------------------------------------------------------------
// mma + cp.async helpers
// ---------------------------------------------------------------------------
__device__ __forceinline__ void mma16816(float* c, const unsigned* a, const unsigned* b) {
    asm volatile(
        "mma.sync.aligned.m16n8k16.row.col.f32.f16.f16.f32 "
        "{%0,%1,%2,%3}, {%4,%5,%6,%7}, {%8,%9}, {%0,%1,%2,%3};\n"
        : "+f"(c[0]), "+f"(c[1]), "+f"(c[2]), "+f"(c[3])
        : "r"(a[0]), "r"(a[1]), "r"(a[2]), "r"(a[3]), "r"(b[0]), "r"(b[1]));
}

__device__ __forceinline__ void cp16(__half* smem, const __half* gmem) {
    unsigned sa = (unsigned)__cvta_generic_to_shared(smem);
    asm volatile("cp.async.ca.shared.global [%0], [%1], 16;\n" :: "r"(sa), "l"(gmem));
}
#define CP_COMMIT() asm volatile("cp.async.commit_group;\n")
#define CP_WAIT0()  asm volatile("cp.async.wait_group 0;\n")
#define CP_WAIT1()  asm volatile("cp.async.wait_group 1;\n")

// ---------------------------------------------------------------------------
// GEMM core, 3-stage cp.async pipeline (BM=128 x BN=64, BK=32)
// ---------------------------------------------------------------------------
__device__ __forceinline__ void gemm_tile(
    const __half* __restrict__ Ag, const __half* __restrict__ Ag2,
    const __half* __restrict__ Bg, int nk,
    __half* As, __half* Bs, float acc[2][4][4])
{
    const int t    = threadIdx.x;
    const int arow = t >> 2, achk = t & 3;
    const int warp = t >> 5, lane = t & 31;
    const int wm   = warp >> 1, wn = warp & 1;
    const int g    = lane >> 2, tg = lane & 3;

    __half* a0p = As + arow * PAD + achk * 8;
    __half* a1p = As + (arow + 64) * PAD + achk * 8;
    __half* b0p = Bs + arow * PAD + achk * 8;

    cp16(a0p, Ag); cp16(a1p, Ag2); cp16(b0p, Bg);
    CP_COMMIT();
    if (nk > 1) {
        cp16(a0p + BM * PAD, Ag + BK);
        cp16(a1p + BM * PAD, Ag2 + BK);
        cp16(b0p + BN * PAD, Bg + BK);
        CP_COMMIT();
    }

    for (int kt = 0; kt < nk; kt++) {
        if (kt == nk - 1) { CP_WAIT0(); } else { CP_WAIT1(); }
        __syncthreads();
        if (kt + 2 < nk) {
            const int st = (kt + 2) % 3;
            cp16(a0p + st * BM * PAD, Ag  + (size_t)(kt + 2) * BK);
            cp16(a1p + st * BM * PAD, Ag2 + (size_t)(kt + 2) * BK);
            cp16(b0p + st * BN * PAD, Bg  + (size_t)(kt + 2) * BK);
            CP_COMMIT();
        }
        const __half* Ac = As + (kt % 3) * BM * PAD;
        const __half* Bc = Bs + (kt % 3) * BN * PAD;
#pragma unroll
        for (int ks = 0; ks < 2; ks++) {
            const int k0 = ks * 16;
            unsigned af[2][4], bf[4][2];
#pragma unroll
            for (int mi = 0; mi < 2; mi++) {
                const __half* base = Ac + (wm * 32 + mi * 16 + g) * PAD + k0 + tg * 2;
                af[mi][0] = *(const unsigned*)base;
                af[mi][1] = *(const unsigned*)(base + 8 * PAD);
                af[mi][2] = *(const unsigned*)(base + 8);
                af[mi][3] = *(const unsigned*)(base + 8 * PAD + 8);
            }
#pragma unroll
            for (int ni = 0; ni < 4; ni++) {
                const __half* base = Bc + (wn * 32 + ni * 8 + g) * PAD + k0 + tg * 2;
                bf[ni][0] = *(const unsigned*)base;
                bf[ni][1] = *(const unsigned*)(base + 8);
            }
#pragma unroll
            for (int mi = 0; mi < 2; mi++)
#pragma unroll
                for (int ni = 0; ni < 4; ni++)
                    mma16816(acc[mi][ni], af[mi], bf[ni]);
        }
    }
}

// ---------------------------------------------------------------------------
// Merged projection GEMM.
// epi: 0 = dual fp16 (Q), 1 = fp16 + bias, 3 = V transposed into g_vT
// ---------------------------------------------------------------------------
struct ProjArgs {
    const __half* A[4];
    const __half* B[4];
    void*         C0[4];
    void*         C1[4];
    const float*  bias[4];
    const float*  ub;
    const float*  vb;
    int           mtiles[4];
    int           epi[4];
};

__global__ __launch_bounds__(256) void proj_kernel(ProjArgs pa) {
    const int z = blockIdx.z;
    if ((int)blockIdx.y >= pa.mtiles[z]) return;

    __shared__ __align__(16) __half As[3 * BM * PAD];
    __shared__ __align__(16) __half Bs[3 * BN * PAD];

    const int t    = threadIdx.x;
    const int m0   = blockIdx.y * BM;
    const int n0   = blockIdx.x * BN;
    const int warp = t >> 5, lane = t & 31;
    const int wm   = warp >> 1, wn = warp & 1;
    const int g    = lane >> 2, tg = lane & 3;
    const int arow = t >> 2, achk = t & 3;

    const __half* A = pa.A[z];
    const __half* Bm = pa.B[z];
    const __half* Ag  = A + (size_t)(m0 + arow) * HIDN + achk * 8;
    const __half* Ag2 = A + (size_t)(m0 + arow + 64) * HIDN + achk * 8;
    const __half* Bg  = Bm + (size_t)(n0 + arow) * HIDN + achk * 8;

    float acc[2][4][4];
#pragma unroll
    for (int mi = 0; mi < 2; mi++)
#pragma unroll
        for (int ni = 0; ni < 4; ni++)
#pragma unroll
            for (int u = 0; u < 4; u++) acc[mi][ni][u] = 0.f;

    gemm_tile(Ag, Ag2, Bg, HIDN / BK, As, Bs, acc);

    const int epi = pa.epi[z];
    const float* bias = pa.bias[z];

    if (epi == 3) {
        __syncthreads();
        __half* Tmp = As;
#pragma unroll
        for (int mi = 0; mi < 2; mi++) {
            const int lr = wm * 32 + mi * 16 + g;
#pragma unroll
            for (int ni = 0; ni < 4; ni++) {
                const int dl = wn * 32 + ni * 8 + tg * 2;
                float* ac = acc[mi][ni];
                const float b0 = bias[n0 + dl], b1 = bias[n0 + dl + 1];
                Tmp[dl * TSTR + lr]           = __float2half(ac[0] + b0);
                Tmp[(dl + 1) * TSTR + lr]     = __float2half(ac[1] + b1);
                Tmp[dl * TSTR + lr + 8]       = __float2half(ac[2] + b0);
                Tmp[(dl + 1) * TSTR + lr + 8] = __float2half(ac[3] + b1);
            }
        }
        __syncthreads();
        const int bb = m0 / LLEN, j0 = m0 % LLEN, h = n0 >> 6;
        __half* vt = g_vT + (size_t)(bb * NHEAD + h) * DHEAD * LLEN;
#pragma unroll
        for (int p = 0; p < 4; p++) {
            const int idx = t + p * 256;
            const int d = idx >> 4, jc = (idx & 15) * 8;
            *(uint4*)(vt + (size_t)d * LLEN + j0 + jc) = *(uint4*)&Tmp[d * TSTR + jc];
        }
        return;
    }

#pragma unroll
    for (int mi = 0; mi < 2; mi++) {
        const int r0 = m0 + wm * 32 + mi * 16 + g;
#pragma unroll
        for (int ni = 0; ni < 4; ni++) {
            const int cb = n0 + wn * 32 + ni * 8 + tg * 2;
            float* ac = acc[mi][ni];
            const size_t o0 = (size_t)r0 * HIDN + cb;
            const size_t o1 = (size_t)(r0 + 8) * HIDN + cb;
            const float b0 = bias[cb], b1 = bias[cb + 1];
            if (epi == 0) {
                const float u0 = 0.125f * (ac[0] + b0 + pa.ub[cb]);
                const float u1 = 0.125f * (ac[1] + b1 + pa.ub[cb + 1]);
                const float u2 = 0.125f * (ac[2] + b0 + pa.ub[cb]);
                const float u3 = 0.125f * (ac[3] + b1 + pa.ub[cb + 1]);
                const float v0 = 0.125f * (ac[0] + b0 + pa.vb[cb]);
                const float v1 = 0.125f * (ac[1] + b1 + pa.vb[cb + 1]);
                const float v2 = 0.125f * (ac[2] + b0 + pa.vb[cb]);
                const float v3 = 0.125f * (ac[3] + b1 + pa.vb[cb + 1]);
                *(__half2*)((__half*)pa.C0[z] + o0) = __floats2half2_rn(u0, u1);
                *(__half2*)((__half*)pa.C0[z] + o1) = __floats2half2_rn(u2, u3);
                *(__half2*)((__half*)pa.C1[z] + o0) = __floats2half2_rn(v0, v1);
                *(__half2*)((__half*)pa.C1[z] + o1) = __floats2half2_rn(v2, v3);
            } else {
                *(__half2*)((__half*)pa.C0[z] + o0) = __floats2half2_rn(ac[0] + b0, ac[1] + b1);
                *(__half2*)((__half*)pa.C0[z] + o1) = __floats2half2_rn(ac[2] + b0, ac[3] + b1);
            }
        }
    }
}

// ---------------------------------------------------------------------------
// Final projection (R12 version): 64x64 tiles, BK=64 stages, 3-stage pipeline.
// grid (8, 48), 256 threads.
// ---------------------------------------------------------------------------
__global__ __launch_bounds__(256) void final_kernel(const __half* __restrict__ A,
                                                    const __half* __restrict__ Bm,
                                                    const float* __restrict__ bias,
                                                    float* __restrict__ C) {
    extern __shared__ __align__(16) __half fdyn[];
    __half* As = fdyn;
    __half* Bs = fdyn + 3 * 64 * FSTR;

    const int t    = threadIdx.x;
    const int m0   = blockIdx.y * 64;
    const int n0   = blockIdx.x * 64;
    const int warp = t >> 5, lane = t & 31;
    const int wm   = warp >> 1, wn = warp & 1;
    const int g    = lane >> 2, tg = lane & 3;
    const int lrow = t >> 3, lchk = (t & 7) * 8;

    const __half* Ag = A  + (size_t)(m0 + lrow) * HIDN + lchk;
    const __half* Bg = Bm + (size_t)(n0 + lrow) * HIDN + lchk;
    __half* a0p = As + lrow * FSTR + lchk;
    __half* b0p = Bs + lrow * FSTR + lchk;

    float acc[4][4];
#pragma unroll
    for (int ni = 0; ni < 4; ni++)
#pragma unroll
        for (int u = 0; u < 4; u++) acc[ni][u] = 0.f;

    const int nst = HIDN / 64;
#pragma unroll
    for (int p = 0; p < 2; p++) {
        const int ro = p * 32;
        cp16(a0p + ro * FSTR, Ag + (size_t)ro * HIDN);
        cp16(b0p + ro * FSTR, Bg + (size_t)ro * HIDN);
    }
    CP_COMMIT();
#pragma unroll
    for (int p = 0; p < 2; p++) {
        const int ro = p * 32;
        cp16(a0p + 64 * FSTR + ro * FSTR, Ag + (size_t)ro * HIDN + 64);
        cp16(b0p + 64 * FSTR + ro * FSTR, Bg + (size_t)ro * HIDN + 64);
    }
    CP_COMMIT();

    for (int st = 0; st < nst; st++) {
        if (st == nst - 1) { CP_WAIT0(); } else { CP_WAIT1(); }
        __syncthreads();
        if (st + 2 < nst) {
            const int sb = ((st + 2) % 3) * 64 * FSTR;
#pragma unroll
            for (int p = 0; p < 2; p++) {
                const int ro = p * 32;
                cp16(a0p + sb + ro * FSTR, Ag + (size_t)ro * HIDN + (st + 2) * 64);
                cp16(b0p + sb + ro * FSTR, Bg + (size_t)ro * HIDN + (st + 2) * 64);
            }
            CP_COMMIT();
        }
        const __half* Ac = As + (st % 3) * 64 * FSTR;
        const __half* Bc = Bs + (st % 3) * 64 * FSTR;
#pragma unroll
        for (int ks = 0; ks < 4; ks++) {
            const int k0 = ks * 16;
            unsigned af[4], bf[4][2];
            const __half* abase = Ac + (wm * 16 + g) * FSTR + k0 + tg * 2;
            af[0] = *(const unsigned*)abase;
            af[1] = *(const unsigned*)(abase + 8 * FSTR);
            af[2] = *(const unsigned*)(abase + 8);
            af[3] = *(const unsigned*)(abase + 8 * FSTR + 8);
#pragma unroll
            for (int ni = 0; ni < 4; ni++) {
                const __half* bbase = Bc + (wn * 32 + ni * 8 + g) * FSTR + k0 + tg * 2;
                bf[ni][0] = *(const unsigned*)bbase;
                bf[ni][1] = *(const unsigned*)(bbase + 8);
            }
#pragma unroll
            for (int ni = 0; ni < 4; ni++)
                mma16816(acc[ni], af, bf[ni]);
        }
    }

    const int r0 = m0 + wm * 16 + g;
#pragma unroll
    for (int ni = 0; ni < 4; ni++) {
        const int cb = n0 + wn * 32 + ni * 8 + tg * 2;
        float* ac = acc[ni];
        const float b0 = bias[cb], b1 = bias[cb + 1];
        *(float2*)(C + (size_t)r0 * HIDN + cb)       = make_float2(ac[0] + b0, ac[1] + b1);
        *(float2*)(C + (size_t)(r0 + 8) * HIDN + cb) = make_float2(ac[2] + b0, ac[3] + b1);
    }
}

// ---------------------------------------------------------------------------
// S-tile compute (n-split): warp computes its 16 rows x 32 cols.
// ---------------------------------------------------------------------------
__device__ __forceinline__ void s_tile_compute(
    const unsigned qvf[4][4], const __half* Rt, __half* Ring,
    int blk, int il_a, int wn, int g, int tg)
{
    float s2[4][4];
#pragma unroll
    for (int ni = 0; ni < 4; ni++)
#pragma unroll
        for (int u = 0; u < 4; u++) s2[ni][u] = 0.f;
#pragma unroll
    for (int ks = 0; ks < 4; ks++) {
        unsigned bf[4][2];
#pragma unroll
        for (int ni = 0; ni < 4; ni++) {
            const __half* base = Rt + (wn * 32 + ni * 8 + g) * ASTR + ks * 16 + tg * 2;
            bf[ni][0] = *(const unsigned*)base;
            bf[ni][1] = *(const unsigned*)(base + 8);
        }
#pragma unroll
        for (int ni = 0; ni < 4; ni++)
            mma16816(s2[ni], qvf[ks], bf[ni]);
    }
#pragma unroll
    for (int ni = 0; ni < 4; ni++) {
        const int c = blk + wn * 32 + ni * 8 + tg * 2;
        *(__half2*)&Ring[il_a * RSTR + c]       = __floats2half2_rn(s2[ni][0], s2[ni][1]);
        *(__half2*)&Ring[(il_a + 8) * RSTR + c] = __floats2half2_rn(s2[ni][2], s2[ni][3]);
    }
}

// ---------------------------------------------------------------------------
// flashA v5: 256 threads, n-split warp pairs (wm rows x wn KV-halves).
// Cross-warp row-max exchange per jt via RedM; O/l combined in epilogue.
// grid (6, 64).
// ---------------------------------------------------------------------------
__global__ __launch_bounds__(256, 2) void flasha_kernel(const int* __restrict__ seq_len) {
    extern __shared__ __align__(16) __half dyn[];
    __half* Ring = dyn;                        // 64*RSTR halves (also float O scratch)
    __half* Qs   = Ring + 64 * RSTR;           // Rbuf[1] alias
    __half* Rb0  = Qs + 64 * ASTR;             // Rbuf[0]
    __half* Ks   = Rb0 + 64 * ASTR;            // 2x
    __half* Vs   = Ks + 2 * 64 * ASTR;         // 2x
    float*  RedM = (float*)(Vs + 2 * 64 * ASTR);  // 2*64 floats

    const int t    = threadIdx.x;
    const int warp = t >> 5, lane = t & 31;
    const int g    = lane >> 2, tg = lane & 3;
    const int wm   = warp & 3, wn = warp >> 2;
    const int bh   = blockIdx.y;
    const int b    = bh >> 3, h = bh & 7;
    const int m0   = blockIdx.x * 64;
    const int sl   = seq_len[b];

    const size_t MB = (size_t)LLEN * HIDN;
    const __half* qub = g_qu + (size_t)b * MB + h * DHEAD;
    const __half* qvb = g_qv + (size_t)b * MB + h * DHEAD;
    const __half* kb  = g_k16 + (size_t)b * MB + h * DHEAD;
    const __half* vTb = g_vT + (size_t)bh * DHEAD * LLEN;
    const __half* rb  = g_r16 + h * DHEAD;
    const int wstart  = 320 - m0;

    const int il_a  = wm * 16 + g;
    const int row_a = m0 + il_a;
    const int row_b = row_a + 8;

    // ---- prologue: qv -> Qs, r0 -> Rb0, K0, V0 ----
#pragma unroll
    for (int p = 0; p < 2; p++) {
        int idx = t + p * 256;
        int row = idx >> 3, col = (idx & 7) * 8;
        cp16(&Qs[row * ASTR + col], qvb + (size_t)(m0 + row) * HIDN + col);
        cp16(&Rb0[row * ASTR + col], rb + (size_t)(wstart + row) * HIDN + col);
        cp16(&Ks[row * ASTR + col], kb + (size_t)row * HIDN + col);
        cp16(&Vs[row * ASTR + col], vTb + (size_t)row * LLEN + col);
    }
    CP_COMMIT(); CP_WAIT0();
    __syncthreads();

    unsigned qvf[4][4];
#pragma unroll
    for (int ks = 0; ks < 4; ks++) {
        const __half* base = &Qs[il_a * ASTR + ks * 16 + tg * 2];
        qvf[ks][0] = *(const unsigned*)base;
        qvf[ks][1] = *(const unsigned*)(base + 8 * ASTR);
        qvf[ks][2] = *(const unsigned*)(base + 8);
        qvf[ks][3] = *(const unsigned*)(base + 8 * ASTR + 8);
    }
    __syncthreads();

#pragma unroll
    for (int p = 0; p < 2; p++) {
        int idx = t + p * 256;
        int row = idx >> 3, col = (idx & 7) * 8;
        cp16(&Qs[row * ASTR + col], qub + (size_t)(m0 + row) * HIDN + col);
    }
    CP_COMMIT(); CP_WAIT0();
    __syncthreads();

    unsigned qf[4][4];
#pragma unroll
    for (int ks = 0; ks < 4; ks++) {
        const __half* base = &Qs[il_a * ASTR + ks * 16 + tg * 2];
        qf[ks][0] = *(const unsigned*)base;
        qf[ks][1] = *(const unsigned*)(base + 8 * ASTR);
        qf[ks][2] = *(const unsigned*)(base + 8);
        qf[ks][3] = *(const unsigned*)(base + 8 * ASTR + 8);
    }
    __syncthreads();

#pragma unroll
    for (int p = 0; p < 2; p++) {
        int idx = t + p * 256;
        int row = idx >> 3, col = (idx & 7) * 8;
        cp16(&Qs[row * ASTR + col], rb + (size_t)(wstart + 64 + row) * HIDN + col);
    }
    CP_COMMIT();

    s_tile_compute(qvf, Rb0, Ring, 0, il_a, wn, g, tg);   // tile 0 -> slot 0

    CP_WAIT0();
    __syncthreads();

    // ---- main flash loop ----
    float O[8][4];
#pragma unroll
    for (int nd = 0; nd < 8; nd++)
#pragma unroll
        for (int u = 0; u < 4; u++) O[nd][u] = 0.f;
    float m_a = -3.0e38f, m_b = -3.0e38f, l_a = 0.f, l_b = 0.f;

    for (int jt = 0; jt < 6; jt++) {
        const int cur = jt & 1;
        if (jt < 5) {
            const int nxt = cur ^ 1;
#pragma unroll
            for (int p = 0; p < 2; p++) {
                int idx = t + p * 256;
                int row = idx >> 3, col = (idx & 7) * 8;
                cp16(&Ks[nxt * 64 * ASTR + row * ASTR + col],
                     kb + (size_t)((jt + 1) * 64 + row) * HIDN + col);
                cp16(&Vs[nxt * 64 * ASTR + row * ASTR + col],
                     vTb + (size_t)row * LLEN + (jt + 1) * 64 + col);
            }
            {
                __half* Rdst = (jt & 1) ? Qs : Rb0;
#pragma unroll
                for (int p = 0; p < 2; p++) {
                    int idx = t + p * 256;
                    int row = idx >> 3, col = (idx & 7) * 8;
                    cp16(&Rdst[row * ASTR + col],
                         rb + (size_t)(wstart + (jt + 2) * 64 + row) * HIDN + col);
                }
            }
            CP_COMMIT();
        }

        // S tile jt+1 -> ring slot (jt+1)&1
        {
            const __half* Rt = ((jt + 1) & 1) ? Qs : Rb0;
            s_tile_compute(qvf, Rt, Ring, ((jt + 1) & 1) * 64, il_a, wn, g, tg);
        }
        __syncthreads();   // ring writes visible (both wn halves)

        // QK score tile: 16 rows x 32 cols (warp's half)
        float s[4][4];
#pragma unroll
        for (int ni = 0; ni < 4; ni++)
#pragma unroll
            for (int u = 0; u < 4; u++) s[ni][u] = 0.f;

        const __half* Kc = Ks + cur * 64 * ASTR;
#pragma unroll
        for (int ks = 0; ks < 4; ks++) {
            unsigned bf[4][2];
#pragma unroll
            for (int ni = 0; ni < 4; ni++) {
                const __half* base = Kc + (wn * 32 + ni * 8 + g) * ASTR + ks * 16 + tg * 2;
                bf[ni][0] = *(const unsigned*)base;
                bf[ni][1] = *(const unsigned*)(base + 8);
            }
#pragma unroll
            for (int ni = 0; ni < 4; ni++)
                mma16816(s[ni], qf[ks], bf[ni]);
        }

        // add shifted S from ring + mask, local max
        const int jtoff = cur * 64;
        const __half* RowA = Ring + il_a * RSTR;
        const __half* RowB = Ring + (il_a + 8) * RSTR;
        float mx_a = m_a, mx_b = m_b;
#pragma unroll
        for (int ni = 0; ni < 4; ni++) {
            const int c0 = wn * 32 + ni * 8 + tg * 2;
            const int j0 = jt * 64 + c0;
            const int offa = c0 - il_a + 64;
            const int offb = offa - 8;
            const float Sa0 = __half2float(RowA[(jtoff + offa)     & 127]);
            const float Sa1 = __half2float(RowA[(jtoff + offa + 1) & 127]);
            const float Sb0 = __half2float(RowB[(jtoff + offb)     & 127]);
            const float Sb1 = __half2float(RowB[(jtoff + offb + 1) & 127]);
            s[ni][0] = (j0     < sl) ? s[ni][0] + Sa0 : -1.0e30f;
            s[ni][1] = (j0 + 1 < sl) ? s[ni][1] + Sa1 : -1.0e30f;
            s[ni][2] = (j0     < sl) ? s[ni][2] + Sb0 : -1.0e30f;
            s[ni][3] = (j0 + 1 < sl) ? s[ni][3] + Sb1 : -1.0e30f;
            mx_a = fmaxf(mx_a, fmaxf(s[ni][0], s[ni][1]));
            mx_b = fmaxf(mx_b, fmaxf(s[ni][2], s[ni][3]));
        }
        mx_a = fmaxf(mx_a, __shfl_xor_sync(0xffffffffu, mx_a, 1));
        mx_a = fmaxf(mx_a, __shfl_xor_sync(0xffffffffu, mx_a, 2));
        mx_b = fmaxf(mx_b, __shfl_xor_sync(0xffffffffu, mx_b, 1));
        mx_b = fmaxf(mx_b, __shfl_xor_sync(0xffffffffu, mx_b, 2));

        // cross-warp max exchange
        if (tg == 0) {
            RedM[wn * 64 + il_a]     = mx_a;
            RedM[wn * 64 + il_a + 8] = mx_b;
        }
        __syncthreads();
        mx_a = fmaxf(mx_a, RedM[(wn ^ 1) * 64 + il_a]);
        mx_b = fmaxf(mx_b, RedM[(wn ^ 1) * 64 + il_a + 8]);

        const float sc_a = __expf(m_a - mx_a);
        const float sc_b = __expf(m_b - mx_b);
        m_a = mx_a; m_b = mx_b;
        l_a *= sc_a; l_b *= sc_b;
#pragma unroll
        for (int nd = 0; nd < 8; nd++) {
            O[nd][0] *= sc_a; O[nd][1] *= sc_a;
            O[nd][2] *= sc_b; O[nd][3] *= sc_b;
        }

        // exp -> P fragments (k = warp's 32 j-cols -> 2 k-steps)
        unsigned pf[2][4];
#pragma unroll
        for (int ni = 0; ni < 4; ni++) {
            const float p0 = __expf(s[ni][0] - m_a);
            const float p1 = __expf(s[ni][1] - m_a);
            const float p2 = __expf(s[ni][2] - m_b);
            const float p3 = __expf(s[ni][3] - m_b);
            l_a += p0 + p1; l_b += p2 + p3;
            const int ks2 = ni >> 1, sub = (ni & 1) * 2;
            const __half2 ha = __floats2half2_rn(p0, p1);
            const __half2 hb = __floats2half2_rn(p2, p3);
            pf[ks2][sub + 0] = *(const unsigned*)&ha;
            pf[ks2][sub + 1] = *(const unsigned*)&hb;
        }

        // PV: partial O over warp's 32 j
        const __half* Vc = Vs + cur * 64 * ASTR;
#pragma unroll
        for (int ks2 = 0; ks2 < 2; ks2++) {
            unsigned vf[8][2];
#pragma unroll
            for (int nd = 0; nd < 8; nd++) {
                const __half* base = Vc + (nd * 8 + g) * ASTR + wn * 32 + ks2 * 16 + tg * 2;
                vf[nd][0] = *(const unsigned*)base;
                vf[nd][1] = *(const unsigned*)(base + 8);
            }
#pragma unroll
            for (int nd = 0; nd < 8; nd++)
                mma16816(O[nd], pf[ks2], vf[nd]);
        }

        if (jt < 5) {
            CP_WAIT0();
            __syncthreads();
        }
    }

    // ---- epilogue: combine partial O and l across wn pairs ----
    __syncthreads();   // ring free for reuse; all RedM traffic done
    float* Osc = (float*)Ring;   // 64 x OSTR floats (17408 B, fits ring)

    // quad-reduce partial l
    l_a += __shfl_xor_sync(0xffffffffu, l_a, 1);
    l_a += __shfl_xor_sync(0xffffffffu, l_a, 2);
    l_b += __shfl_xor_sync(0xffffffffu, l_b, 1);
    l_b += __shfl_xor_sync(0xffffffffu, l_b, 2);

    if (wn == 1) {
#pragma unroll
        for (int nd = 0; nd < 8; nd++) {
            const int c = nd * 8 + tg * 2;
            Osc[il_a * OSTR + c]           = O[nd][0];
            Osc[il_a * OSTR + c + 1]       = O[nd][1];
            Osc[(il_a + 8) * OSTR + c]     = O[nd][2];
            Osc[(il_a + 8) * OSTR + c + 1] = O[nd][3];
        }
        if (tg == 0) {
            RedM[il_a]     = l_a;
            RedM[il_a + 8] = l_b;
        }
    }
    __syncthreads();

    if (wn == 0) {
        const float inv_a = 1.f / (l_a + RedM[il_a]);
        const float inv_b = 1.f / (l_b + RedM[il_a + 8]);
        __half* Cb = g_ctx16 + (size_t)b * MB + h * DHEAD;
#pragma unroll
        for (int nd = 0; nd < 8; nd++) {
            const int c = nd * 8 + tg * 2;
            const float o0 = (O[nd][0] + Osc[il_a * OSTR + c])           * inv_a;
            const float o1 = (O[nd][1] + Osc[il_a * OSTR + c + 1])       * inv_a;
            const float o2 = (O[nd][2] + Osc[(il_a + 8) * OSTR + c])     * inv_b;
            const float o3 = (O[nd][3] + Osc[(il_a + 8) * OSTR + c + 1]) * inv_b;
            *(__half2*)(Cb + (size_t)row_a * HIDN + c) = __floats2half2_rn(o0, o1);
            *(__half2*)(Cb + (size_t)row_b * HIDN + c) = __floats2half2_rn(o2, o3);
        }
    }
}

// ---------------------------------------------------------------------------
// Launcher
// ---------------------------------------------------------------------------
extern "C" void kernel_launch(void* const* d_in, const int* in_sizes, int n_in,
                              void* d_out, int out_size) {
    const float* key    = (const float*)d_in[0];
    const float* query  = (const float*)d_in[1];
    const float* value  = (const float*)d_in[2];
    const int*   seqlen = (const int*)  d_in[3];
    const float* pe     = (const float*)d_in[4];
    const float* Wk = (const float*)d_in[5],  *bk = (const float*)d_in[6];
    const float* Wq = (const float*)d_in[7],  *bq = (const float*)d_in[8];
    const float* Wv = (const float*)d_in[9],  *bv = (const float*)d_in[10];
    const float* Wr = (const float*)d_in[11], *br = (const float*)d_in[12];
    const float* u_bias = (const float*)d_in[13];
    const float* v_bias = (const float*)d_in[14];
    const float* Wf = (const float*)d_in[15], *bf = (const float*)d_in[16];
    float* out = (float*)d_out;

    __half *xk, *xq, *xv, *pe16, *wq16, *wk16, *wv16, *wr16, *wf16;
    __half *qu, *qv, *k16, *r16, *ctx16;
    cudaGetSymbolAddress((void**)&xk,   g_xk);
    cudaGetSymbolAddress((void**)&xq,   g_xq);
    cudaGetSymbolAddress((void**)&xv,   g_xv);
    cudaGetSymbolAddress((void**)&pe16, g_pe16);
    cudaGetSymbolAddress((void**)&wq16, g_wq16);
    cudaGetSymbolAddress((void**)&wk16, g_wk16);
    cudaGetSymbolAddress((void**)&wv16, g_wv16);
    cudaGetSymbolAddress((void**)&wr16, g_wr16);
    cudaGetSymbolAddress((void**)&wf16, g_wf16);
    cudaGetSymbolAddress((void**)&qu,   g_qu);
    cudaGetSymbolAddress((void**)&qv,   g_qv);
    cudaGetSymbolAddress((void**)&k16,  g_k16);
    cudaGetSymbolAddress((void**)&r16,  g_r16);
    cudaGetSymbolAddress((void**)&ctx16,g_ctx16);

    const int dynBytes = (64 * RSTR + 6 * 64 * ASTR) * (int)sizeof(__half)
                       + 2 * 64 * (int)sizeof(float);
    cudaFuncSetAttribute(flasha_kernel, cudaFuncAttributeMaxDynamicSharedMemorySize, dynBytes);
    const int finBytes = 6 * 64 * FSTR * (int)sizeof(__half);
    cudaFuncSetAttribute(final_kernel, cudaFuncAttributeMaxDynamicSharedMemorySize, finBytes);

    // 1. convert everything to fp16 (flattened)
    CvtArgs ca;
    ca.src[0] = key;   ca.dst[0] = xk;
    ca.src[1] = query; ca.dst[1] = xq;
    ca.src[2] = value; ca.dst[2] = xv;
    ca.src[3] = pe;    ca.dst[3] = pe16;
    ca.src[4] = Wq;    ca.dst[4] = wq16;
    ca.src[5] = Wk;    ca.dst[5] = wk16;
    ca.src[6] = Wv;    ca.dst[6] = wv16;
    ca.src[7] = Wr;    ca.dst[7] = wr16;
    ca.src[8] = Wf;    ca.dst[8] = wf16;
    {
        const int sizes[9] = {BB*LLEN*HIDN, BB*LLEN*HIDN, BB*LLEN*HIDN,
                              PROWS*HIDN, HIDN*HIDN, HIDN*HIDN, HIDN*HIDN,
                              HIDN*HIDN, HIDN*HIDN};
        int c = 0;
        for (int i = 0; i < 9; i++) { ca.cum[i] = c; c += sizes[i]; }
        ca.cum[9] = c;
        const int nblk = (c / 8 + 255) / 256;
        cvt_kernel<<<nblk, 256>>>(ca);
    }

    // 2. merged projections: Q (dual), K, V (transposed epilogue), R
    ProjArgs pj;
    pj.A[0] = xq;   pj.B[0] = wq16; pj.C0[0] = qu;  pj.C1[0] = qv;
    pj.bias[0] = bq; pj.mtiles[0] = 24; pj.epi[0] = 0;
    pj.A[1] = xk;   pj.B[1] = wk16; pj.C0[1] = k16; pj.C1[1] = nullptr;
    pj.bias[1] = bk; pj.mtiles[1] = 24; pj.epi[1] = 1;
    pj.A[2] = xv;   pj.B[2] = wv16; pj.C0[2] = nullptr; pj.C1[2] = nullptr;
    pj.bias[2] = bv; pj.mtiles[2] = 24; pj.epi[2] = 3;
    pj.A[3] = pe16; pj.B[3] = wr16; pj.C0[3] = r16; pj.C1[3] = nullptr;
    pj.bias[3] = br; pj.mtiles[3] = 6;  pj.epi[3] = 1;
    pj.ub = u_bias; pj.vb = v_bias;
    proj_kernel<<<dim3(HIDN / BN, 24, 4), 256>>>(pj);

    // 3. fused flash attention (256-thread n-split) -> ctx16
    flasha_kernel<<<dim3(LLEN / 64, NBH), 256, dynBytes>>>(seqlen);

    // 4. final projection (BK=64 pipeline) -> fp32 out
    final_kernel<<<dim3(HIDN / 64, (BB * LLEN) / 64), 256, finBytes>>>(ctx16, wf16, bf, out);
}

// round 16
// speedup vs baseline: 1.5665x; 1.5665x over previous
#include <cuda_runtime.h>
#include <cuda_fp16.h>
#include <math.h>

// Problem constants
#define BB    8
#define LLEN  384
#define HIDN  512
#define NHEAD 8
#define DHEAD 64
#define PROWS 768
#define NBH   (BB*NHEAD)

// GEMM tile config
#define BM 128
#define BN 64
#define BK 32
#define PAD 40   // smem row stride in halves
#define ASTR 72  // 64-wide tile stride (halves)
#define RSTR 136 // ring row stride (halves)
#define TSTR 136 // V-transpose staging stride (halves)
#define FSTR 72  // final kernel stage stride (halves)

// ---------------------------------------------------------------------------
// Scratch (device globals)
// ---------------------------------------------------------------------------
__device__ __half g_xk[BB*LLEN*HIDN];
__device__ __half g_xq[BB*LLEN*HIDN];
__device__ __half g_xv[BB*LLEN*HIDN];
__device__ __half g_pe16[PROWS*HIDN];
__device__ __half g_wq16[HIDN*HIDN];
__device__ __half g_wk16[HIDN*HIDN];
__device__ __half g_wv16[HIDN*HIDN];
__device__ __half g_wr16[HIDN*HIDN];
__device__ __half g_wf16[HIDN*HIDN];

__device__ __half g_qu[BB*LLEN*HIDN];
__device__ __half g_qv[BB*LLEN*HIDN];
__device__ __half g_k16[BB*LLEN*HIDN];
__device__ __half g_r16[PROWS*HIDN];
__device__ __half g_vT[NBH*DHEAD*LLEN];
__device__ __half g_ctx16[BB*LLEN*HIDN];

// ---------------------------------------------------------------------------
// fp32 -> fp16 convert (flattened)
// ---------------------------------------------------------------------------
struct CvtArgs {
    const float* src[9];
    __half*      dst[9];
    int          cum[10];
};

__global__ __launch_bounds__(256) void cvt_kernel(CvtArgs a) {
    const int gi = (blockIdx.x * 256 + threadIdx.x) * 8;
    if (gi >= a.cum[9]) return;
    int ti = 0;
#pragma unroll
    for (int k = 1; k < 9; k++) ti += (gi >= a.cum[k]) ? 1 : 0;
    const int off = gi - a.cum[ti];
    const float4* s = (const float4*)(a.src[ti] + off);
    float4 x = s[0], y = s[1];
    __half2 h0 = __floats2half2_rn(x.x, x.y);
    __half2 h1 = __floats2half2_rn(x.z, x.w);
    __half2 h2 = __floats2half2_rn(y.x, y.y);
    __half2 h3 = __floats2half2_rn(y.z, y.w);
    uint4 o;
    o.x = *(unsigned*)&h0; o.y = *(unsigned*)&h1;
    o.z = *(unsigned*)&h2; o.w = *(unsigned*)&h3;
    *(uint4*)(a.dst[ti] + off) = o;
}

// ---------------------------------------------------------------------------
// mma + cp.async helpers
// ---------------------------------------------------------------------------
__device__ __forceinline__ void mma16816(float* c, const unsigned* a, const unsigned* b) {
    asm volatile(
        "mma.sync.aligned.m16n8k16.row.col.f32.f16.f16.f32 "
        "{%0,%1,%2,%3}, {%4,%5,%6,%7}, {%8,%9}, {%0,%1,%2,%3};\n"
        : "+f"(c[0]), "+f"(c[1]), "+f"(c[2]), "+f"(c[3])
        : "r"(a[0]), "r"(a[1]), "r"(a[2]), "r"(a[3]), "r"(b[0]), "r"(b[1]));
}

__device__ __forceinline__ void cp16(__half* smem, const __half* gmem) {
    unsigned sa = (unsigned)__cvta_generic_to_shared(smem);
    asm volatile("cp.async.ca.shared.global [%0], [%1], 16;\n" :: "r"(sa), "l"(gmem));
}
#define CP_COMMIT() asm volatile("cp.async.commit_group;\n")
#define CP_WAIT0()  asm volatile("cp.async.wait_group 0;\n")
#define CP_WAIT1()  asm volatile("cp.async.wait_group 1;\n")

// ---------------------------------------------------------------------------
// GEMM core, 3-stage cp.async pipeline (BM=128 x BN=64, BK=32)
// ---------------------------------------------------------------------------
__device__ __forceinline__ void gemm_tile(
    const __half* __restrict__ Ag, const __half* __restrict__ Ag2,
    const __half* __restrict__ Bg, int nk,
    __half* As, __half* Bs, float acc[2][4][4])
{
    const int t    = threadIdx.x;
    const int arow = t >> 2, achk = t & 3;
    const int warp = t >> 5, lane = t & 31;
    const int wm   = warp >> 1, wn = warp & 1;
    const int g    = lane >> 2, tg = lane & 3;

    __half* a0p = As + arow * PAD + achk * 8;
    __half* a1p = As + (arow + 64) * PAD + achk * 8;
    __half* b0p = Bs + arow * PAD + achk * 8;

    cp16(a0p, Ag); cp16(a1p, Ag2); cp16(b0p, Bg);
    CP_COMMIT();
    if (nk > 1) {
        cp16(a0p + BM * PAD, Ag + BK);
        cp16(a1p + BM * PAD, Ag2 + BK);
        cp16(b0p + BN * PAD, Bg + BK);
        CP_COMMIT();
    }

    for (int kt = 0; kt < nk; kt++) {
        if (kt == nk - 1) { CP_WAIT0(); } else { CP_WAIT1(); }
        __syncthreads();
        if (kt + 2 < nk) {
            const int st = (kt + 2) % 3;
            cp16(a0p + st * BM * PAD, Ag  + (size_t)(kt + 2) * BK);
            cp16(a1p + st * BM * PAD, Ag2 + (size_t)(kt + 2) * BK);
            cp16(b0p + st * BN * PAD, Bg  + (size_t)(kt + 2) * BK);
            CP_COMMIT();
        }
        const __half* Ac = As + (kt % 3) * BM * PAD;
        const __half* Bc = Bs + (kt % 3) * BN * PAD;
#pragma unroll
        for (int ks = 0; ks < 2; ks++) {
            const int k0 = ks * 16;
            unsigned af[2][4], bf[4][2];
#pragma unroll
            for (int mi = 0; mi < 2; mi++) {
                const __half* base = Ac + (wm * 32 + mi * 16 + g) * PAD + k0 + tg * 2;
                af[mi][0] = *(const unsigned*)base;
                af[mi][1] = *(const unsigned*)(base + 8 * PAD);
                af[mi][2] = *(const unsigned*)(base + 8);
                af[mi][3] = *(const unsigned*)(base + 8 * PAD + 8);
            }
#pragma unroll
            for (int ni = 0; ni < 4; ni++) {
                const __half* base = Bc + (wn * 32 + ni * 8 + g) * PAD + k0 + tg * 2;
                bf[ni][0] = *(const unsigned*)base;
                bf[ni][1] = *(const unsigned*)(base + 8);
            }
#pragma unroll
            for (int mi = 0; mi < 2; mi++)
#pragma unroll
                for (int ni = 0; ni < 4; ni++)
                    mma16816(acc[mi][ni], af[mi], bf[ni]);
        }
    }
}

// ---------------------------------------------------------------------------
// Merged projection GEMM.
// epi: 0 = dual fp16 (Q), 1 = fp16 + bias, 3 = V transposed into g_vT
// ---------------------------------------------------------------------------
struct ProjArgs {
    const __half* A[4];
    const __half* B[4];
    void*         C0[4];
    void*         C1[4];
    const float*  bias[4];
    const float*  ub;
    const float*  vb;
    int           mtiles[4];
    int           epi[4];
};

__global__ __launch_bounds__(256) void proj_kernel(ProjArgs pa) {
    const int z = blockIdx.z;
    if ((int)blockIdx.y >= pa.mtiles[z]) return;

    __shared__ __align__(16) __half As[3 * BM * PAD];
    __shared__ __align__(16) __half Bs[3 * BN * PAD];

    const int t    = threadIdx.x;
    const int m0   = blockIdx.y * BM;
    const int n0   = blockIdx.x * BN;
    const int warp = t >> 5, lane = t & 31;
    const int wm   = warp >> 1, wn = warp & 1;
    const int g    = lane >> 2, tg = lane & 3;
    const int arow = t >> 2, achk = t & 3;

    const __half* A = pa.A[z];
    const __half* Bm = pa.B[z];
    const __half* Ag  = A + (size_t)(m0 + arow) * HIDN + achk * 8;
    const __half* Ag2 = A + (size_t)(m0 + arow + 64) * HIDN + achk * 8;
    const __half* Bg  = Bm + (size_t)(n0 + arow) * HIDN + achk * 8;

    float acc[2][4][4];
#pragma unroll
    for (int mi = 0; mi < 2; mi++)
#pragma unroll
        for (int ni = 0; ni < 4; ni++)
#pragma unroll
            for (int u = 0; u < 4; u++) acc[mi][ni][u] = 0.f;

    gemm_tile(Ag, Ag2, Bg, HIDN / BK, As, Bs, acc);

    const int epi = pa.epi[z];
    const float* bias = pa.bias[z];

    if (epi == 3) {
        __syncthreads();
        __half* Tmp = As;
#pragma unroll
        for (int mi = 0; mi < 2; mi++) {
            const int lr = wm * 32 + mi * 16 + g;
#pragma unroll
            for (int ni = 0; ni < 4; ni++) {
                const int dl = wn * 32 + ni * 8 + tg * 2;
                float* ac = acc[mi][ni];
                const float b0 = bias[n0 + dl], b1 = bias[n0 + dl + 1];
                Tmp[dl * TSTR + lr]           = __float2half(ac[0] + b0);
                Tmp[(dl + 1) * TSTR + lr]     = __float2half(ac[1] + b1);
                Tmp[dl * TSTR + lr + 8]       = __float2half(ac[2] + b0);
                Tmp[(dl + 1) * TSTR + lr + 8] = __float2half(ac[3] + b1);
            }
        }
        __syncthreads();
        const int bb = m0 / LLEN, j0 = m0 % LLEN, h = n0 >> 6;
        __half* vt = g_vT + (size_t)(bb * NHEAD + h) * DHEAD * LLEN;
#pragma unroll
        for (int p = 0; p < 4; p++) {
            const int idx = t + p * 256;
            const int d = idx >> 4, jc = (idx & 15) * 8;
            *(uint4*)(vt + (size_t)d * LLEN + j0 + jc) = *(uint4*)&Tmp[d * TSTR + jc];
        }
        return;
    }

#pragma unroll
    for (int mi = 0; mi < 2; mi++) {
        const int r0 = m0 + wm * 32 + mi * 16 + g;
#pragma unroll
        for (int ni = 0; ni < 4; ni++) {
            const int cb = n0 + wn * 32 + ni * 8 + tg * 2;
            float* ac = acc[mi][ni];
            const size_t o0 = (size_t)r0 * HIDN + cb;
            const size_t o1 = (size_t)(r0 + 8) * HIDN + cb;
            const float b0 = bias[cb], b1 = bias[cb + 1];
            if (epi == 0) {
                const float u0 = 0.125f * (ac[0] + b0 + pa.ub[cb]);
                const float u1 = 0.125f * (ac[1] + b1 + pa.ub[cb + 1]);
                const float u2 = 0.125f * (ac[2] + b0 + pa.ub[cb]);
                const float u3 = 0.125f * (ac[3] + b1 + pa.ub[cb + 1]);
                const float v0 = 0.125f * (ac[0] + b0 + pa.vb[cb]);
                const float v1 = 0.125f * (ac[1] + b1 + pa.vb[cb + 1]);
                const float v2 = 0.125f * (ac[2] + b0 + pa.vb[cb]);
                const float v3 = 0.125f * (ac[3] + b1 + pa.vb[cb + 1]);
                *(__half2*)((__half*)pa.C0[z] + o0) = __floats2half2_rn(u0, u1);
                *(__half2*)((__half*)pa.C0[z] + o1) = __floats2half2_rn(u2, u3);
                *(__half2*)((__half*)pa.C1[z] + o0) = __floats2half2_rn(v0, v1);
                *(__half2*)((__half*)pa.C1[z] + o1) = __floats2half2_rn(v2, v3);
            } else {
                *(__half2*)((__half*)pa.C0[z] + o0) = __floats2half2_rn(ac[0] + b0, ac[1] + b1);
                *(__half2*)((__half*)pa.C0[z] + o1) = __floats2half2_rn(ac[2] + b0, ac[3] + b1);
            }
        }
    }
}

// ---------------------------------------------------------------------------
// Final projection: 64x64 tiles, BK=64 stages, 3-stage pipeline. grid (8,48).
// ---------------------------------------------------------------------------
__global__ __launch_bounds__(256) void final_kernel(const __half* __restrict__ A,
                                                    const __half* __restrict__ Bm,
                                                    const float* __restrict__ bias,
                                                    float* __restrict__ C) {
    extern __shared__ __align__(16) __half fdyn[];
    __half* As = fdyn;
    __half* Bs = fdyn + 3 * 64 * FSTR;

    const int t    = threadIdx.x;
    const int m0   = blockIdx.y * 64;
    const int n0   = blockIdx.x * 64;
    const int warp = t >> 5, lane = t & 31;
    const int wm   = warp >> 1, wn = warp & 1;
    const int g    = lane >> 2, tg = lane & 3;
    const int lrow = t >> 3, lchk = (t & 7) * 8;

    const __half* Ag = A  + (size_t)(m0 + lrow) * HIDN + lchk;
    const __half* Bg = Bm + (size_t)(n0 + lrow) * HIDN + lchk;
    __half* a0p = As + lrow * FSTR + lchk;
    __half* b0p = Bs + lrow * FSTR + lchk;

    float acc[4][4];
#pragma unroll
    for (int ni = 0; ni < 4; ni++)
#pragma unroll
        for (int u = 0; u < 4; u++) acc[ni][u] = 0.f;

    const int nst = HIDN / 64;
#pragma unroll
    for (int p = 0; p < 2; p++) {
        const int ro = p * 32;
        cp16(a0p + ro * FSTR, Ag + (size_t)ro * HIDN);
        cp16(b0p + ro * FSTR, Bg + (size_t)ro * HIDN);
    }
    CP_COMMIT();
#pragma unroll
    for (int p = 0; p < 2; p++) {
        const int ro = p * 32;
        cp16(a0p + 64 * FSTR + ro * FSTR, Ag + (size_t)ro * HIDN + 64);
        cp16(b0p + 64 * FSTR + ro * FSTR, Bg + (size_t)ro * HIDN + 64);
    }
    CP_COMMIT();

    for (int st = 0; st < nst; st++) {
        if (st == nst - 1) { CP_WAIT0(); } else { CP_WAIT1(); }
        __syncthreads();
        if (st + 2 < nst) {
            const int sb = ((st + 2) % 3) * 64 * FSTR;
#pragma unroll
            for (int p = 0; p < 2; p++) {
                const int ro = p * 32;
                cp16(a0p + sb + ro * FSTR, Ag + (size_t)ro * HIDN + (st + 2) * 64);
                cp16(b0p + sb + ro * FSTR, Bg + (size_t)ro * HIDN + (st + 2) * 64);
            }
            CP_COMMIT();
        }
        const __half* Ac = As + (st % 3) * 64 * FSTR;
        const __half* Bc = Bs + (st % 3) * 64 * FSTR;
#pragma unroll
        for (int ks = 0; ks < 4; ks++) {
            const int k0 = ks * 16;
            unsigned af[4], bf[4][2];
            const __half* abase = Ac + (wm * 16 + g) * FSTR + k0 + tg * 2;
            af[0] = *(const unsigned*)abase;
            af[1] = *(const unsigned*)(abase + 8 * FSTR);
            af[2] = *(const unsigned*)(abase + 8);
            af[3] = *(const unsigned*)(abase + 8 * FSTR + 8);
#pragma unroll
            for (int ni = 0; ni < 4; ni++) {
                const __half* bbase = Bc + (wn * 32 + ni * 8 + g) * FSTR + k0 + tg * 2;
                bf[ni][0] = *(const unsigned*)bbase;
                bf[ni][1] = *(const unsigned*)(bbase + 8);
            }
#pragma unroll
            for (int ni = 0; ni < 4; ni++)
                mma16816(acc[ni], af, bf[ni]);
        }
    }

    const int r0 = m0 + wm * 16 + g;
#pragma unroll
    for (int ni = 0; ni < 4; ni++) {
        const int cb = n0 + wn * 32 + ni * 8 + tg * 2;
        float* ac = acc[ni];
        const float b0 = bias[cb], b1 = bias[cb + 1];
        *(float2*)(C + (size_t)r0 * HIDN + cb)       = make_float2(ac[0] + b0, ac[1] + b1);
        *(float2*)(C + (size_t)(r0 + 8) * HIDN + cb) = make_float2(ac[2] + b0, ac[3] + b1);
    }
}

// ---------------------------------------------------------------------------
// S-tile compute: one 64x64 window tile = qv @ r16_tile^T into ring slot.
// ---------------------------------------------------------------------------
__device__ __forceinline__ void s_tile_compute(
    const unsigned qvf[4][4], const __half* Rt, __half* Ring,
    int blk, int il_a, int g, int tg)
{
    float s2[8][4];
#pragma unroll
    for (int ni = 0; ni < 8; ni++)
#pragma unroll
        for (int u = 0; u < 4; u++) s2[ni][u] = 0.f;
#pragma unroll
    for (int ks = 0; ks < 4; ks++) {
        unsigned bf[8][2];
#pragma unroll
        for (int ni = 0; ni < 8; ni++) {
            const __half* base = Rt + (ni * 8 + g) * ASTR + ks * 16 + tg * 2;
            bf[ni][0] = *(const unsigned*)base;
            bf[ni][1] = *(const unsigned*)(base + 8);
        }
#pragma unroll
        for (int ni = 0; ni < 8; ni++)
            mma16816(s2[ni], qvf[ks], bf[ni]);
    }
#pragma unroll
    for (int ni = 0; ni < 8; ni++) {
        const int c = blk + ni * 8 + tg * 2;
        *(__half2*)&Ring[il_a * RSTR + c]       = __floats2half2_rn(s2[ni][0], s2[ni][1]);
        *(__half2*)&Ring[(il_a + 8) * RSTR + c] = __floats2half2_rn(s2[ni][2], s2[ni][3]);
    }
}

// ---------------------------------------------------------------------------
// flashA v4.1: rolling S ring, inline S tiles, merged single-wait prologue
// (qu staged through Ks slot 1, dead until jt=0 prefetch).
// block = 128 threads (4 warps x 16 rows).  grid = (6, 64).
// ---------------------------------------------------------------------------
__global__ __launch_bounds__(128, 3) void flasha_kernel(const int* __restrict__ seq_len) {
    extern __shared__ __align__(16) __half dyn[];
    __half* Ring = dyn;
    __half* Qs   = Ring + 64 * RSTR;
    __half* Rb0  = Qs + 64 * ASTR;
    __half* Ks   = Rb0 + 64 * ASTR;
    __half* Vs   = Ks + 2 * 64 * ASTR;

    const int t    = threadIdx.x;
    const int warp = t >> 5, lane = t & 31;
    const int g    = lane >> 2, tg = lane & 3;
    const int bh   = blockIdx.y;
    const int b    = bh >> 3, h = bh & 7;
    const int m0   = blockIdx.x * 64;
    const int sl   = seq_len[b];

    const size_t MB = (size_t)LLEN * HIDN;
    const __half* qub = g_qu + (size_t)b * MB + h * DHEAD;
    const __half* qvb = g_qv + (size_t)b * MB + h * DHEAD;
    const __half* kb  = g_k16 + (size_t)b * MB + h * DHEAD;
    const __half* vTb = g_vT + (size_t)bh * DHEAD * LLEN;
    const __half* rb  = g_r16 + h * DHEAD;
    const int wstart  = 320 - m0;

    const int il_a  = warp * 16 + g;
    const int row_a = m0 + il_a;
    const int row_b = row_a + 8;

    // ---- merged prologue: one group for qv, qu (->Ks slot1), r0, K0, V0 ----
    __half* QuStage = Ks + 64 * ASTR;   // Ks slot 1: free until jt=0 prefetch
#pragma unroll
    for (int p = 0; p < 4; p++) {
        int idx = t + p * 128;
        int row = idx >> 3, col = (idx & 7) * 8;
        cp16(&Qs[row * ASTR + col],      qvb + (size_t)(m0 + row) * HIDN + col);
        cp16(&QuStage[row * ASTR + col], qub + (size_t)(m0 + row) * HIDN + col);
        cp16(&Rb0[row * ASTR + col],     rb + (size_t)(wstart + row) * HIDN + col);
        cp16(&Ks[row * ASTR + col],      kb + (size_t)row * HIDN + col);
        cp16(&Vs[row * ASTR + col],      vTb + (size_t)row * LLEN + col);
    }
    CP_COMMIT(); CP_WAIT0();
    __syncthreads();

    unsigned qvf[4][4], qf[4][4];
#pragma unroll
    for (int ks = 0; ks < 4; ks++) {
        const __half* base = &Qs[il_a * ASTR + ks * 16 + tg * 2];
        qvf[ks][0] = *(const unsigned*)base;
        qvf[ks][1] = *(const unsigned*)(base + 8 * ASTR);
        qvf[ks][2] = *(const unsigned*)(base + 8);
        qvf[ks][3] = *(const unsigned*)(base + 8 * ASTR + 8);
        const __half* ubase = &QuStage[il_a * ASTR + ks * 16 + tg * 2];
        qf[ks][0] = *(const unsigned*)ubase;
        qf[ks][1] = *(const unsigned*)(ubase + 8 * ASTR);
        qf[ks][2] = *(const unsigned*)(ubase + 8);
        qf[ks][3] = *(const unsigned*)(ubase + 8 * ASTR + 8);
    }
    __syncthreads();   // fragments extracted; Qs and Ks slot1 reusable

    // ---- stage: r1 -> Qs (Rbuf[1]); compute S tile 0 meanwhile ----
#pragma unroll
    for (int p = 0; p < 4; p++) {
        int idx = t + p * 128;
        int row = idx >> 3, col = (idx & 7) * 8;
        cp16(&Qs[row * ASTR + col], rb + (size_t)(wstart + 64 + row) * HIDN + col);
    }
    CP_COMMIT();

    s_tile_compute(qvf, Rb0, Ring, 0, il_a, g, tg);

    CP_WAIT0();
    __syncthreads();

    // ---- main flash loop ----
    float O[8][4];
#pragma unroll
    for (int nd = 0; nd < 8; nd++)
#pragma unroll
        for (int u = 0; u < 4; u++) O[nd][u] = 0.f;
    float m_a = -3.0e38f, m_b = -3.0e38f, l_a = 0.f, l_b = 0.f;

    for (int jt = 0; jt < 6; jt++) {
        const int cur = jt & 1;
        if (jt < 5) {
            const int nxt = cur ^ 1;
#pragma unroll
            for (int p = 0; p < 4; p++) {
                int idx = t + p * 128;
                int row = idx >> 3, col = (idx & 7) * 8;
                cp16(&Ks[nxt * 64 * ASTR + row * ASTR + col],
                     kb + (size_t)((jt + 1) * 64 + row) * HIDN + col);
                cp16(&Vs[nxt * 64 * ASTR + row * ASTR + col],
                     vTb + (size_t)row * LLEN + (jt + 1) * 64 + col);
            }
            {
                __half* Rdst = (jt & 1) ? Qs : Rb0;
#pragma unroll
                for (int p = 0; p < 4; p++) {
                    int idx = t + p * 128;
                    int row = idx >> 3, col = (idx & 7) * 8;
                    cp16(&Rdst[row * ASTR + col],
                         rb + (size_t)(wstart + (jt + 2) * 64 + row) * HIDN + col);
                }
            }
            CP_COMMIT();
        }

        {
            const __half* Rt = ((jt + 1) & 1) ? Qs : Rb0;
            s_tile_compute(qvf, Rt, Ring, ((jt + 1) & 1) * 64, il_a, g, tg);
        }

        float s[8][4];
#pragma unroll
        for (int ni = 0; ni < 8; ni++)
#pragma unroll
            for (int u = 0; u < 4; u++) s[ni][u] = 0.f;

        const __half* Kc = Ks + cur * 64 * ASTR;
#pragma unroll
        for (int ks = 0; ks < 4; ks++) {
            unsigned bf[8][2];
#pragma unroll
            for (int ni = 0; ni < 8; ni++) {
                const __half* base = Kc + (ni * 8 + g) * ASTR + ks * 16 + tg * 2;
                bf[ni][0] = *(const unsigned*)base;
                bf[ni][1] = *(const unsigned*)(base + 8);
            }
#pragma unroll
            for (int ni = 0; ni < 8; ni++)
                mma16816(s[ni], qf[ks], bf[ni]);
        }

        const int jtoff = cur * 64;
        const __half* RowA = Ring + il_a * RSTR;
        const __half* RowB = Ring + (il_a + 8) * RSTR;
        float mx_a = m_a, mx_b = m_b;
#pragma unroll
        for (int ni = 0; ni < 8; ni++) {
            const int c0 = ni * 8 + tg * 2;
            const int j0 = jt * 64 + c0;
            const int offa = c0 - il_a + 64;
            const int offb = offa - 8;
            const float Sa0 = __half2float(RowA[(jtoff + offa)     & 127]);
            const float Sa1 = __half2float(RowA[(jtoff + offa + 1) & 127]);
            const float Sb0 = __half2float(RowB[(jtoff + offb)     & 127]);
            const float Sb1 = __half2float(RowB[(jtoff + offb + 1) & 127]);
            s[ni][0] = (j0     < sl) ? s[ni][0] + Sa0 : -1.0e30f;
            s[ni][1] = (j0 + 1 < sl) ? s[ni][1] + Sa1 : -1.0e30f;
            s[ni][2] = (j0     < sl) ? s[ni][2] + Sb0 : -1.0e30f;
            s[ni][3] = (j0 + 1 < sl) ? s[ni][3] + Sb1 : -1.0e30f;
            mx_a = fmaxf(mx_a, fmaxf(s[ni][0], s[ni][1]));
            mx_b = fmaxf(mx_b, fmaxf(s[ni][2], s[ni][3]));
        }
        mx_a = fmaxf(mx_a, __shfl_xor_sync(0xffffffffu, mx_a, 1));
        mx_a = fmaxf(mx_a, __shfl_xor_sync(0xffffffffu, mx_a, 2));
        mx_b = fmaxf(mx_b, __shfl_xor_sync(0xffffffffu, mx_b, 1));
        mx_b = fmaxf(mx_b, __shfl_xor_sync(0xffffffffu, mx_b, 2));

        const float sc_a = __expf(m_a - mx_a);
        const float sc_b = __expf(m_b - mx_b);
        m_a = mx_a; m_b = mx_b;
        l_a *= sc_a; l_b *= sc_b;
#pragma unroll
        for (int nd = 0; nd < 8; nd++) {
            O[nd][0] *= sc_a; O[nd][1] *= sc_a;
            O[nd][2] *= sc_b; O[nd][3] *= sc_b;
        }

        unsigned pf[4][4];
#pragma unroll
        for (int ni = 0; ni < 8; ni++) {
            const float p0 = __expf(s[ni][0] - m_a);
            const float p1 = __expf(s[ni][1] - m_a);
            const float p2 = __expf(s[ni][2] - m_b);
            const float p3 = __expf(s[ni][3] - m_b);
            l_a += p0 + p1; l_b += p2 + p3;
            const int ks = ni >> 1, sub = (ni & 1) * 2;
            const __half2 ha = __floats2half2_rn(p0, p1);
            const __half2 hb = __floats2half2_rn(p2, p3);
            pf[ks][sub + 0] = *(const unsigned*)&ha;
            pf[ks][sub + 1] = *(const unsigned*)&hb;
        }

        const __half* Vc = Vs + cur * 64 * ASTR;
#pragma unroll
        for (int ks = 0; ks < 4; ks++) {
            unsigned vf[8][2];
#pragma unroll
            for (int nd = 0; nd < 8; nd++) {
                const __half* base = Vc + (nd * 8 + g) * ASTR + ks * 16 + tg * 2;
                vf[nd][0] = *(const unsigned*)base;
                vf[nd][1] = *(const unsigned*)(base + 8);
            }
#pragma unroll
            for (int nd = 0; nd < 8; nd++)
                mma16816(O[nd], pf[ks], vf[nd]);
        }

        if (jt < 5) {
            CP_WAIT0();
            __syncthreads();
        }
    }

    l_a += __shfl_xor_sync(0xffffffffu, l_a, 1);
    l_a += __shfl_xor_sync(0xffffffffu, l_a, 2);
    l_b += __shfl_xor_sync(0xffffffffu, l_b, 1);
    l_b += __shfl_xor_sync(0xffffffffu, l_b, 2);
    const float inv_a = 1.f / l_a;
    const float inv_b = 1.f / l_b;

    __half* Cb = g_ctx16 + (size_t)b * MB + h * DHEAD;
#pragma unroll
    for (int nd = 0; nd < 8; nd++) {
        const int c = nd * 8 + tg * 2;
        *(__half2*)(Cb + (size_t)row_a * HIDN + c) =
            __floats2half2_rn(O[nd][0] * inv_a, O[nd][1] * inv_a);
        *(__half2*)(Cb + (size_t)row_b * HIDN + c) =
            __floats2half2_rn(O[nd][2] * inv_b, O[nd][3] * inv_b);
    }
}

// ---------------------------------------------------------------------------
// Launcher
// ---------------------------------------------------------------------------
extern "C" void kernel_launch(void* const* d_in, const int* in_sizes, int n_in,
                              void* d_out, int out_size) {
    const float* key    = (const float*)d_in[0];
    const float* query  = (const float*)d_in[1];
    const float* value  = (const float*)d_in[2];
    const int*   seqlen = (const int*)  d_in[3];
    const float* pe     = (const float*)d_in[4];
    const float* Wk = (const float*)d_in[5],  *bk = (const float*)d_in[6];
    const float* Wq = (const float*)d_in[7],  *bq = (const float*)d_in[8];
    const float* Wv = (const float*)d_in[9],  *bv = (const float*)d_in[10];
    const float* Wr = (const float*)d_in[11], *br = (const float*)d_in[12];
    const float* u_bias = (const float*)d_in[13];
    const float* v_bias = (const float*)d_in[14];
    const float* Wf = (const float*)d_in[15], *bf = (const float*)d_in[16];
    float* out = (float*)d_out;

    __half *xk, *xq, *xv, *pe16, *wq16, *wk16, *wv16, *wr16, *wf16;
    __half *qu, *qv, *k16, *r16, *ctx16;
    cudaGetSymbolAddress((void**)&xk,   g_xk);
    cudaGetSymbolAddress((void**)&xq,   g_xq);
    cudaGetSymbolAddress((void**)&xv,   g_xv);
    cudaGetSymbolAddress((void**)&pe16, g_pe16);
    cudaGetSymbolAddress((void**)&wq16, g_wq16);
    cudaGetSymbolAddress((void**)&wk16, g_wk16);
    cudaGetSymbolAddress((void**)&wv16, g_wv16);
    cudaGetSymbolAddress((void**)&wr16, g_wr16);
    cudaGetSymbolAddress((void**)&wf16, g_wf16);
    cudaGetSymbolAddress((void**)&qu,   g_qu);
    cudaGetSymbolAddress((void**)&qv,   g_qv);
    cudaGetSymbolAddress((void**)&k16,  g_k16);
    cudaGetSymbolAddress((void**)&r16,  g_r16);
    cudaGetSymbolAddress((void**)&ctx16,g_ctx16);

    const int dynBytes = (64 * RSTR + 6 * 64 * ASTR) * (int)sizeof(__half);
    cudaFuncSetAttribute(flasha_kernel, cudaFuncAttributeMaxDynamicSharedMemorySize, dynBytes);
    const int finBytes = 6 * 64 * FSTR * (int)sizeof(__half);
    cudaFuncSetAttribute(final_kernel, cudaFuncAttributeMaxDynamicSharedMemorySize, finBytes);

    // 1. convert everything to fp16 (flattened)
    CvtArgs ca;
    ca.src[0] = key;   ca.dst[0] = xk;
    ca.src[1] = query; ca.dst[1] = xq;
    ca.src[2] = value; ca.dst[2] = xv;
    ca.src[3] = pe;    ca.dst[3] = pe16;
    ca.src[4] = Wq;    ca.dst[4] = wq16;
    ca.src[5] = Wk;    ca.dst[5] = wk16;
    ca.src[6] = Wv;    ca.dst[6] = wv16;
    ca.src[7] = Wr;    ca.dst[7] = wr16;
    ca.src[8] = Wf;    ca.dst[8] = wf16;
    {
        const int sizes[9] = {BB*LLEN*HIDN, BB*LLEN*HIDN, BB*LLEN*HIDN,
                              PROWS*HIDN, HIDN*HIDN, HIDN*HIDN, HIDN*HIDN,
                              HIDN*HIDN, HIDN*HIDN};
        int c = 0;
        for (int i = 0; i < 9; i++) { ca.cum[i] = c; c += sizes[i]; }
        ca.cum[9] = c;
        const int nblk = (c / 8 + 255) / 256;
        cvt_kernel<<<nblk, 256>>>(ca);
    }

    // 2. merged projections: Q (dual), K, V (transposed epilogue), R
    ProjArgs pj;
    pj.A[0] = xq;   pj.B[0] = wq16; pj.C0[0] = qu;  pj.C1[0] = qv;
    pj.bias[0] = bq; pj.mtiles[0] = 24; pj.epi[0] = 0;
    pj.A[1] = xk;   pj.B[1] = wk16; pj.C0[1] = k16; pj.C1[1] = nullptr;
    pj.bias[1] = bk; pj.mtiles[1] = 24; pj.epi[1] = 1;
    pj.A[2] = xv;   pj.B[2] = wv16; pj.C0[2] = nullptr; pj.C1[2] = nullptr;
    pj.bias[2] = bv; pj.mtiles[2] = 24; pj.epi[2] = 3;
    pj.A[3] = pe16; pj.B[3] = wr16; pj.C0[3] = r16; pj.C1[3] = nullptr;
    pj.bias[3] = br; pj.mtiles[3] = 6;  pj.epi[3] = 1;
    pj.ub = u_bias; pj.vb = v_bias;
    proj_kernel<<<dim3(HIDN / BN, 24, 4), 256>>>(pj);

    // 3. fused flash attention -> ctx16
    flasha_kernel<<<dim3(LLEN / 64, NBH), 128, dynBytes>>>(seqlen);

    // 4. final projection (BK=64 pipeline) -> fp32 out
    final_kernel<<<dim3(HIDN / 64, (BB * LLEN) / 64), 256, finBytes>>>(ctx16, wf16, bf, out);
}

// round 17
// speedup vs baseline: 1.6138x; 1.0302x over previous
#include <cuda_runtime.h>
#include <cuda_fp16.h>
#include <math.h>

// Problem constants
#define BB    8
#define LLEN  384
#define HIDN  512
#define NHEAD 8
#define DHEAD 64
#define PROWS 768
#define NBH   (BB*NHEAD)

// GEMM tile config
#define BM 128
#define BN 64
#define BK 32
#define PAD 40   // smem row stride in halves
#define ASTR 72  // 64-wide tile stride (halves)
#define RSTR 136 // ring row stride (halves)
#define TSTR 136 // V-transpose staging stride (halves)
#define FSTR 72  // final kernel stage stride (halves)

// ---------------------------------------------------------------------------
// Scratch (device globals)
// ---------------------------------------------------------------------------
__device__ __half g_xk[BB*LLEN*HIDN];
__device__ __half g_xq[BB*LLEN*HIDN];
__device__ __half g_xv[BB*LLEN*HIDN];
__device__ __half g_pe16[PROWS*HIDN];
__device__ __half g_wq16[HIDN*HIDN];
__device__ __half g_wk16[HIDN*HIDN];
__device__ __half g_wv16[HIDN*HIDN];
__device__ __half g_wr16[HIDN*HIDN];
__device__ __half g_wf16[HIDN*HIDN];

__device__ __half g_qu[BB*LLEN*HIDN];
__device__ __half g_qv[BB*LLEN*HIDN];
__device__ __half g_k16[BB*LLEN*HIDN];
__device__ __half g_r16[PROWS*HIDN];
__device__ __half g_vT[NBH*DHEAD*LLEN];
__device__ __half g_ctx16[BB*LLEN*HIDN];

// ---------------------------------------------------------------------------
// fp32 -> fp16 convert (flattened)
// ---------------------------------------------------------------------------
struct CvtArgs {
    const float* src[9];
    __half*      dst[9];
    int          cum[10];
};

__global__ __launch_bounds__(256) void cvt_kernel(CvtArgs a) {
    const int gi = (blockIdx.x * 256 + threadIdx.x) * 8;
    if (gi >= a.cum[9]) return;
    int ti = 0;
#pragma unroll
    for (int k = 1; k < 9; k++) ti += (gi >= a.cum[k]) ? 1 : 0;
    const int off = gi - a.cum[ti];
    const float4* s = (const float4*)(a.src[ti] + off);
    float4 x = s[0], y = s[1];
    __half2 h0 = __floats2half2_rn(x.x, x.y);
    __half2 h1 = __floats2half2_rn(x.z, x.w);
    __half2 h2 = __floats2half2_rn(y.x, y.y);
    __half2 h3 = __floats2half2_rn(y.z, y.w);
    uint4 o;
    o.x = *(unsigned*)&h0; o.y = *(unsigned*)&h1;
    o.z = *(unsigned*)&h2; o.w = *(unsigned*)&h3;
    *(uint4*)(a.dst[ti] + off) = o;
}

// ---------------------------------------------------------------------------
// mma + cp.async helpers
// ---------------------------------------------------------------------------
__device__ __forceinline__ void mma16816(float* c, const unsigned* a, const unsigned* b) {
    asm volatile(
        "mma.sync.aligned.m16n8k16.row.col.f32.f16.f16.f32 "
        "{%0,%1,%2,%3}, {%4,%5,%6,%7}, {%8,%9}, {%0,%1,%2,%3};\n"
        : "+f"(c[0]), "+f"(c[1]), "+f"(c[2]), "+f"(c[3])
        : "r"(a[0]), "r"(a[1]), "r"(a[2]), "r"(a[3]), "r"(b[0]), "r"(b[1]));
}

__device__ __forceinline__ void cp16(__half* smem, const __half* gmem) {
    unsigned sa = (unsigned)__cvta_generic_to_shared(smem);
    asm volatile("cp.async.ca.shared.global [%0], [%1], 16;\n" :: "r"(sa), "l"(gmem));
}
#define CP_COMMIT() asm volatile("cp.async.commit_group;\n")
#define CP_WAIT0()  asm volatile("cp.async.wait_group 0;\n")
#define CP_WAIT1()  asm volatile("cp.async.wait_group 1;\n")

// ---------------------------------------------------------------------------
// GEMM core, 3-stage cp.async pipeline (BM=128 x BN=64, BK=32)
// ---------------------------------------------------------------------------
__device__ __forceinline__ void gemm_tile(
    const __half* __restrict__ Ag, const __half* __restrict__ Ag2,
    const __half* __restrict__ Bg, int nk,
    __half* As, __half* Bs, float acc[2][4][4])
{
    const int t    = threadIdx.x;
    const int arow = t >> 2, achk = t & 3;
    const int warp = t >> 5, lane = t & 31;
    const int wm   = warp >> 1, wn = warp & 1;
    const int g    = lane >> 2, tg = lane & 3;

    __half* a0p = As + arow * PAD + achk * 8;
    __half* a1p = As + (arow + 64) * PAD + achk * 8;
    __half* b0p = Bs + arow * PAD + achk * 8;

    cp16(a0p, Ag); cp16(a1p, Ag2); cp16(b0p, Bg);
    CP_COMMIT();
    if (nk > 1) {
        cp16(a0p + BM * PAD, Ag + BK);
        cp16(a1p + BM * PAD, Ag2 + BK);
        cp16(b0p + BN * PAD, Bg + BK);
        CP_COMMIT();
    }

    for (int kt = 0; kt < nk; kt++) {
        if (kt == nk - 1) { CP_WAIT0(); } else { CP_WAIT1(); }
        __syncthreads();
        if (kt + 2 < nk) {
            const int st = (kt + 2) % 3;
            cp16(a0p + st * BM * PAD, Ag  + (size_t)(kt + 2) * BK);
            cp16(a1p + st * BM * PAD, Ag2 + (size_t)(kt + 2) * BK);
            cp16(b0p + st * BN * PAD, Bg  + (size_t)(kt + 2) * BK);
            CP_COMMIT();
        }
        const __half* Ac = As + (kt % 3) * BM * PAD;
        const __half* Bc = Bs + (kt % 3) * BN * PAD;
#pragma unroll
        for (int ks = 0; ks < 2; ks++) {
            const int k0 = ks * 16;
            unsigned af[2][4], bf[4][2];
#pragma unroll
            for (int mi = 0; mi < 2; mi++) {
                const __half* base = Ac + (wm * 32 + mi * 16 + g) * PAD + k0 + tg * 2;
                af[mi][0] = *(const unsigned*)base;
                af[mi][1] = *(const unsigned*)(base + 8 * PAD);
                af[mi][2] = *(const unsigned*)(base + 8);
                af[mi][3] = *(const unsigned*)(base + 8 * PAD + 8);
            }
#pragma unroll
            for (int ni = 0; ni < 4; ni++) {
                const __half* base = Bc + (wn * 32 + ni * 8 + g) * PAD + k0 + tg * 2;
                bf[ni][0] = *(const unsigned*)base;
                bf[ni][1] = *(const unsigned*)(base + 8);
            }
#pragma unroll
            for (int mi = 0; mi < 2; mi++)
#pragma unroll
                for (int ni = 0; ni < 4; ni++)
                    mma16816(acc[mi][ni], af[mi], bf[ni]);
        }
    }
}

// ---------------------------------------------------------------------------
// Merged projection GEMM.
// epi: 0 = dual fp16 (Q), 1 = fp16 + bias, 3 = V transposed into g_vT
// ---------------------------------------------------------------------------
struct ProjArgs {
    const __half* A[4];
    const __half* B[4];
    void*         C0[4];
    void*         C1[4];
    const float*  bias[4];
    const float*  ub;
    const float*  vb;
    int           mtiles[4];
    int           epi[4];
};

__global__ __launch_bounds__(256) void proj_kernel(ProjArgs pa) {
    const int z = blockIdx.z;
    if ((int)blockIdx.y >= pa.mtiles[z]) return;

    __shared__ __align__(16) __half As[3 * BM * PAD];
    __shared__ __align__(16) __half Bs[3 * BN * PAD];

    const int t    = threadIdx.x;
    const int m0   = blockIdx.y * BM;
    const int n0   = blockIdx.x * BN;
    const int warp = t >> 5, lane = t & 31;
    const int wm   = warp >> 1, wn = warp & 1;
    const int g    = lane >> 2, tg = lane & 3;
    const int arow = t >> 2, achk = t & 3;

    const __half* A = pa.A[z];
    const __half* Bm = pa.B[z];
    const __half* Ag  = A + (size_t)(m0 + arow) * HIDN + achk * 8;
    const __half* Ag2 = A + (size_t)(m0 + arow + 64) * HIDN + achk * 8;
    const __half* Bg  = Bm + (size_t)(n0 + arow) * HIDN + achk * 8;

    float acc[2][4][4];
#pragma unroll
    for (int mi = 0; mi < 2; mi++)
#pragma unroll
        for (int ni = 0; ni < 4; ni++)
#pragma unroll
            for (int u = 0; u < 4; u++) acc[mi][ni][u] = 0.f;

    gemm_tile(Ag, Ag2, Bg, HIDN / BK, As, Bs, acc);

    const int epi = pa.epi[z];
    const float* bias = pa.bias[z];

    if (epi == 3) {
        __syncthreads();
        __half* Tmp = As;
#pragma unroll
        for (int mi = 0; mi < 2; mi++) {
            const int lr = wm * 32 + mi * 16 + g;
#pragma unroll
            for (int ni = 0; ni < 4; ni++) {
                const int dl = wn * 32 + ni * 8 + tg * 2;
                float* ac = acc[mi][ni];
                const float b0 = bias[n0 + dl], b1 = bias[n0 + dl + 1];
                Tmp[dl * TSTR + lr]           = __float2half(ac[0] + b0);
                Tmp[(dl + 1) * TSTR + lr]     = __float2half(ac[1] + b1);
                Tmp[dl * TSTR + lr + 8]       = __float2half(ac[2] + b0);
                Tmp[(dl + 1) * TSTR + lr + 8] = __float2half(ac[3] + b1);
            }
        }
        __syncthreads();
        const int bb = m0 / LLEN, j0 = m0 % LLEN, h = n0 >> 6;
        __half* vt = g_vT + (size_t)(bb * NHEAD + h) * DHEAD * LLEN;
#pragma unroll
        for (int p = 0; p < 4; p++) {
            const int idx = t + p * 256;
            const int d = idx >> 4, jc = (idx & 15) * 8;
            *(uint4*)(vt + (size_t)d * LLEN + j0 + jc) = *(uint4*)&Tmp[d * TSTR + jc];
        }
        return;
    }

#pragma unroll
    for (int mi = 0; mi < 2; mi++) {
        const int r0 = m0 + wm * 32 + mi * 16 + g;
#pragma unroll
        for (int ni = 0; ni < 4; ni++) {
            const int cb = n0 + wn * 32 + ni * 8 + tg * 2;
            float* ac = acc[mi][ni];
            const size_t o0 = (size_t)r0 * HIDN + cb;
            const size_t o1 = (size_t)(r0 + 8) * HIDN + cb;
            const float b0 = bias[cb], b1 = bias[cb + 1];
            if (epi == 0) {
                const float u0 = 0.125f * (ac[0] + b0 + pa.ub[cb]);
                const float u1 = 0.125f * (ac[1] + b1 + pa.ub[cb + 1]);
                const float u2 = 0.125f * (ac[2] + b0 + pa.ub[cb]);
                const float u3 = 0.125f * (ac[3] + b1 + pa.ub[cb + 1]);
                const float v0 = 0.125f * (ac[0] + b0 + pa.vb[cb]);
                const float v1 = 0.125f * (ac[1] + b1 + pa.vb[cb + 1]);
                const float v2 = 0.125f * (ac[2] + b0 + pa.vb[cb]);
                const float v3 = 0.125f * (ac[3] + b1 + pa.vb[cb + 1]);
                *(__half2*)((__half*)pa.C0[z] + o0) = __floats2half2_rn(u0, u1);
                *(__half2*)((__half*)pa.C0[z] + o1) = __floats2half2_rn(u2, u3);
                *(__half2*)((__half*)pa.C1[z] + o0) = __floats2half2_rn(v0, v1);
                *(__half2*)((__half*)pa.C1[z] + o1) = __floats2half2_rn(v2, v3);
            } else {
                *(__half2*)((__half*)pa.C0[z] + o0) = __floats2half2_rn(ac[0] + b0, ac[1] + b1);
                *(__half2*)((__half*)pa.C0[z] + o1) = __floats2half2_rn(ac[2] + b0, ac[3] + b1);
            }
        }
    }
}

// ---------------------------------------------------------------------------
// Final projection: 64x64 tiles, BK=64 stages, 3-stage pipeline. grid (8,48).
// ---------------------------------------------------------------------------
__global__ __launch_bounds__(256) void final_kernel(const __half* __restrict__ A,
                                                    const __half* __restrict__ Bm,
                                                    const float* __restrict__ bias,
                                                    float* __restrict__ C) {
    extern __shared__ __align__(16) __half fdyn[];
    __half* As = fdyn;
    __half* Bs = fdyn + 3 * 64 * FSTR;

    const int t    = threadIdx.x;
    const int m0   = blockIdx.y * 64;
    const int n0   = blockIdx.x * 64;
    const int warp = t >> 5, lane = t & 31;
    const int wm   = warp >> 1, wn = warp & 1;
    const int g    = lane >> 2, tg = lane & 3;
    const int lrow = t >> 3, lchk = (t & 7) * 8;

    const __half* Ag = A  + (size_t)(m0 + lrow) * HIDN + lchk;
    const __half* Bg = Bm + (size_t)(n0 + lrow) * HIDN + lchk;
    __half* a0p = As + lrow * FSTR + lchk;
    __half* b0p = Bs + lrow * FSTR + lchk;

    float acc[4][4];
#pragma unroll
    for (int ni = 0; ni < 4; ni++)
#pragma unroll
        for (int u = 0; u < 4; u++) acc[ni][u] = 0.f;

    const int nst = HIDN / 64;
#pragma unroll
    for (int p = 0; p < 2; p++) {
        const int ro = p * 32;
        cp16(a0p + ro * FSTR, Ag + (size_t)ro * HIDN);
        cp16(b0p + ro * FSTR, Bg + (size_t)ro * HIDN);
    }
    CP_COMMIT();
#pragma unroll
    for (int p = 0; p < 2; p++) {
        const int ro = p * 32;
        cp16(a0p + 64 * FSTR + ro * FSTR, Ag + (size_t)ro * HIDN + 64);
        cp16(b0p + 64 * FSTR + ro * FSTR, Bg + (size_t)ro * HIDN + 64);
    }
    CP_COMMIT();

    for (int st = 0; st < nst; st++) {
        if (st == nst - 1) { CP_WAIT0(); } else { CP_WAIT1(); }
        __syncthreads();
        if (st + 2 < nst) {
            const int sb = ((st + 2) % 3) * 64 * FSTR;
#pragma unroll
            for (int p = 0; p < 2; p++) {
                const int ro = p * 32;
                cp16(a0p + sb + ro * FSTR, Ag + (size_t)ro * HIDN + (st + 2) * 64);
                cp16(b0p + sb + ro * FSTR, Bg + (size_t)ro * HIDN + (st + 2) * 64);
            }
            CP_COMMIT();
        }
        const __half* Ac = As + (st % 3) * 64 * FSTR;
        const __half* Bc = Bs + (st % 3) * 64 * FSTR;
#pragma unroll
        for (int ks = 0; ks < 4; ks++) {
            const int k0 = ks * 16;
            unsigned af[4], bf[4][2];
            const __half* abase = Ac + (wm * 16 + g) * FSTR + k0 + tg * 2;
            af[0] = *(const unsigned*)abase;
            af[1] = *(const unsigned*)(abase + 8 * FSTR);
            af[2] = *(const unsigned*)(abase + 8);
            af[3] = *(const unsigned*)(abase + 8 * FSTR + 8);
#pragma unroll
            for (int ni = 0; ni < 4; ni++) {
                const __half* bbase = Bc + (wn * 32 + ni * 8 + g) * FSTR + k0 + tg * 2;
                bf[ni][0] = *(const unsigned*)bbase;
                bf[ni][1] = *(const unsigned*)(bbase + 8);
            }
#pragma unroll
            for (int ni = 0; ni < 4; ni++)
                mma16816(acc[ni], af, bf[ni]);
        }
    }

    const int r0 = m0 + wm * 16 + g;
#pragma unroll
    for (int ni = 0; ni < 4; ni++) {
        const int cb = n0 + wn * 32 + ni * 8 + tg * 2;
        float* ac = acc[ni];
        const float b0 = bias[cb], b1 = bias[cb + 1];
        *(float2*)(C + (size_t)r0 * HIDN + cb)       = make_float2(ac[0] + b0, ac[1] + b1);
        *(float2*)(C + (size_t)(r0 + 8) * HIDN + cb) = make_float2(ac[2] + b0, ac[3] + b1);
    }
}

// ---------------------------------------------------------------------------
// S-tile compute: one 64x64 window tile = qv @ r16_tile^T into ring slot.
// ---------------------------------------------------------------------------
__device__ __forceinline__ void s_tile_compute(
    const unsigned qvf[4][4], const __half* Rt, __half* Ring,
    int blk, int il_a, int g, int tg)
{
    float s2[8][4];
#pragma unroll
    for (int ni = 0; ni < 8; ni++)
#pragma unroll
        for (int u = 0; u < 4; u++) s2[ni][u] = 0.f;
#pragma unroll
    for (int ks = 0; ks < 4; ks++) {
        unsigned bf[8][2];
#pragma unroll
        for (int ni = 0; ni < 8; ni++) {
            const __half* base = Rt + (ni * 8 + g) * ASTR + ks * 16 + tg * 2;
            bf[ni][0] = *(const unsigned*)base;
            bf[ni][1] = *(const unsigned*)(base + 8);
        }
#pragma unroll
        for (int ni = 0; ni < 8; ni++)
            mma16816(s2[ni], qvf[ks], bf[ni]);
    }
#pragma unroll
    for (int ni = 0; ni < 8; ni++) {
        const int c = blk + ni * 8 + tg * 2;
        *(__half2*)&Ring[il_a * RSTR + c]       = __floats2half2_rn(s2[ni][0], s2[ni][1]);
        *(__half2*)&Ring[(il_a + 8) * RSTR + c] = __floats2half2_rn(s2[ni][2], s2[ni][3]);
    }
}

// ---------------------------------------------------------------------------
// flashA v4.2: rolling S ring, inline S tiles, merged prologue, and
// seq_len-aware KV-tile skipping (jtN = ceil(sl/64); fully-masked tiles
// contribute exactly zero, so skipping them is bit-identical).
// block = 128 threads (4 warps x 16 rows).  grid = (6, 64).
// ---------------------------------------------------------------------------
__global__ __launch_bounds__(128, 3) void flasha_kernel(const int* __restrict__ seq_len) {
    extern __shared__ __align__(16) __half dyn[];
    __half* Ring = dyn;
    __half* Qs   = Ring + 64 * RSTR;
    __half* Rb0  = Qs + 64 * ASTR;
    __half* Ks   = Rb0 + 64 * ASTR;
    __half* Vs   = Ks + 2 * 64 * ASTR;

    const int t    = threadIdx.x;
    const int warp = t >> 5, lane = t & 31;
    const int g    = lane >> 2, tg = lane & 3;
    const int bh   = blockIdx.y;
    const int b    = bh >> 3, h = bh & 7;
    const int m0   = blockIdx.x * 64;
    const int sl   = seq_len[b];
    const int jtN  = min(6, (sl + 63) >> 6);   // tiles with any unmasked j

    const size_t MB = (size_t)LLEN * HIDN;
    const __half* qub = g_qu + (size_t)b * MB + h * DHEAD;
    const __half* qvb = g_qv + (size_t)b * MB + h * DHEAD;
    const __half* kb  = g_k16 + (size_t)b * MB + h * DHEAD;
    const __half* vTb = g_vT + (size_t)bh * DHEAD * LLEN;
    const __half* rb  = g_r16 + h * DHEAD;
    const int wstart  = 320 - m0;

    const int il_a  = warp * 16 + g;
    const int row_a = m0 + il_a;
    const int row_b = row_a + 8;

    // ---- merged prologue: one group for qv, qu (->Ks slot1), r0, K0, V0 ----
    __half* QuStage = Ks + 64 * ASTR;
#pragma unroll
    for (int p = 0; p < 4; p++) {
        int idx = t + p * 128;
        int row = idx >> 3, col = (idx & 7) * 8;
        cp16(&Qs[row * ASTR + col],      qvb + (size_t)(m0 + row) * HIDN + col);
        cp16(&QuStage[row * ASTR + col], qub + (size_t)(m0 + row) * HIDN + col);
        cp16(&Rb0[row * ASTR + col],     rb + (size_t)(wstart + row) * HIDN + col);
        cp16(&Ks[row * ASTR + col],      kb + (size_t)row * HIDN + col);
        cp16(&Vs[row * ASTR + col],      vTb + (size_t)row * LLEN + col);
    }
    CP_COMMIT(); CP_WAIT0();
    __syncthreads();

    unsigned qvf[4][4], qf[4][4];
#pragma unroll
    for (int ks = 0; ks < 4; ks++) {
        const __half* base = &Qs[il_a * ASTR + ks * 16 + tg * 2];
        qvf[ks][0] = *(const unsigned*)base;
        qvf[ks][1] = *(const unsigned*)(base + 8 * ASTR);
        qvf[ks][2] = *(const unsigned*)(base + 8);
        qvf[ks][3] = *(const unsigned*)(base + 8 * ASTR + 8);
        const __half* ubase = &QuStage[il_a * ASTR + ks * 16 + tg * 2];
        qf[ks][0] = *(const unsigned*)ubase;
        qf[ks][1] = *(const unsigned*)(ubase + 8 * ASTR);
        qf[ks][2] = *(const unsigned*)(ubase + 8);
        qf[ks][3] = *(const unsigned*)(ubase + 8 * ASTR + 8);
    }
    __syncthreads();

    // ---- stage: r1 -> Qs (Rbuf[1]); compute S tile 0 meanwhile ----
#pragma unroll
    for (int p = 0; p < 4; p++) {
        int idx = t + p * 128;
        int row = idx >> 3, col = (idx & 7) * 8;
        cp16(&Qs[row * ASTR + col], rb + (size_t)(wstart + 64 + row) * HIDN + col);
    }
    CP_COMMIT();

    s_tile_compute(qvf, Rb0, Ring, 0, il_a, g, tg);

    CP_WAIT0();
    __syncthreads();

    // ---- main flash loop over unmasked KV tiles only ----
    float O[8][4];
#pragma unroll
    for (int nd = 0; nd < 8; nd++)
#pragma unroll
        for (int u = 0; u < 4; u++) O[nd][u] = 0.f;
    float m_a = -3.0e38f, m_b = -3.0e38f, l_a = 0.f, l_b = 0.f;

    for (int jt = 0; jt < jtN; jt++) {
        const int cur = jt & 1;
        if (jt + 1 < jtN) {
            const int nxt = cur ^ 1;
#pragma unroll
            for (int p = 0; p < 4; p++) {
                int idx = t + p * 128;
                int row = idx >> 3, col = (idx & 7) * 8;
                cp16(&Ks[nxt * 64 * ASTR + row * ASTR + col],
                     kb + (size_t)((jt + 1) * 64 + row) * HIDN + col);
                cp16(&Vs[nxt * 64 * ASTR + row * ASTR + col],
                     vTb + (size_t)row * LLEN + (jt + 1) * 64 + col);
            }
            {
                __half* Rdst = (jt & 1) ? Qs : Rb0;
#pragma unroll
                for (int p = 0; p < 4; p++) {
                    int idx = t + p * 128;
                    int row = idx >> 3, col = (idx & 7) * 8;
                    cp16(&Rdst[row * ASTR + col],
                         rb + (size_t)(wstart + (jt + 2) * 64 + row) * HIDN + col);
                }
            }
            CP_COMMIT();
        }

        // S tile jt+1 (band at jt spans window tiles jt and jt+1)
        {
            const __half* Rt = ((jt + 1) & 1) ? Qs : Rb0;
            s_tile_compute(qvf, Rt, Ring, ((jt + 1) & 1) * 64, il_a, g, tg);
        }

        float s[8][4];
#pragma unroll
        for (int ni = 0; ni < 8; ni++)
#pragma unroll
            for (int u = 0; u < 4; u++) s[ni][u] = 0.f;

        const __half* Kc = Ks + cur * 64 * ASTR;
#pragma unroll
        for (int ks = 0; ks < 4; ks++) {
            unsigned bf[8][2];
#pragma unroll
            for (int ni = 0; ni < 8; ni++) {
                const __half* base = Kc + (ni * 8 + g) * ASTR + ks * 16 + tg * 2;
                bf[ni][0] = *(const unsigned*)base;
                bf[ni][1] = *(const unsigned*)(base + 8);
            }
#pragma unroll
            for (int ni = 0; ni < 8; ni++)
                mma16816(s[ni], qf[ks], bf[ni]);
        }

        const int jtoff = cur * 64;
        const __half* RowA = Ring + il_a * RSTR;
        const __half* RowB = Ring + (il_a + 8) * RSTR;
        float mx_a = m_a, mx_b = m_b;
#pragma unroll
        for (int ni = 0; ni < 8; ni++) {
            const int c0 = ni * 8 + tg * 2;
            const int j0 = jt * 64 + c0;
            const int offa = c0 - il_a + 64;
            const int offb = offa - 8;
            const float Sa0 = __half2float(RowA[(jtoff + offa)     & 127]);
            const float Sa1 = __half2float(RowA[(jtoff + offa + 1) & 127]);
            const float Sb0 = __half2float(RowB[(jtoff + offb)     & 127]);
            const float Sb1 = __half2float(RowB[(jtoff + offb + 1) & 127]);
            s[ni][0] = (j0     < sl) ? s[ni][0] + Sa0 : -1.0e30f;
            s[ni][1] = (j0 + 1 < sl) ? s[ni][1] + Sa1 : -1.0e30f;
            s[ni][2] = (j0     < sl) ? s[ni][2] + Sb0 : -1.0e30f;
            s[ni][3] = (j0 + 1 < sl) ? s[ni][3] + Sb1 : -1.0e30f;
            mx_a = fmaxf(mx_a, fmaxf(s[ni][0], s[ni][1]));
            mx_b = fmaxf(mx_b, fmaxf(s[ni][2], s[ni][3]));
        }
        mx_a = fmaxf(mx_a, __shfl_xor_sync(0xffffffffu, mx_a, 1));
        mx_a = fmaxf(mx_a, __shfl_xor_sync(0xffffffffu, mx_a, 2));
        mx_b = fmaxf(mx_b, __shfl_xor_sync(0xffffffffu, mx_b, 1));
        mx_b = fmaxf(mx_b, __shfl_xor_sync(0xffffffffu, mx_b, 2));

        const float sc_a = __expf(m_a - mx_a);
        const float sc_b = __expf(m_b - mx_b);
        m_a = mx_a; m_b = mx_b;
        l_a *= sc_a; l_b *= sc_b;
#pragma unroll
        for (int nd = 0; nd < 8; nd++) {
            O[nd][0] *= sc_a; O[nd][1] *= sc_a;
            O[nd][2] *= sc_b; O[nd][3] *= sc_b;
        }

        unsigned pf[4][4];
#pragma unroll
        for (int ni = 0; ni < 8; ni++) {
            const float p0 = __expf(s[ni][0] - m_a);
            const float p1 = __expf(s[ni][1] - m_a);
            const float p2 = __expf(s[ni][2] - m_b);
            const float p3 = __expf(s[ni][3] - m_b);
            l_a += p0 + p1; l_b += p2 + p3;
            const int ks = ni >> 1, sub = (ni & 1) * 2;
            const __half2 ha = __floats2half2_rn(p0, p1);
            const __half2 hb = __floats2half2_rn(p2, p3);
            pf[ks][sub + 0] = *(const unsigned*)&ha;
            pf[ks][sub + 1] = *(const unsigned*)&hb;
        }

        const __half* Vc = Vs + cur * 64 * ASTR;
#pragma unroll
        for (int ks = 0; ks < 4; ks++) {
            unsigned vf[8][2];
#pragma unroll
            for (int nd = 0; nd < 8; nd++) {
                const __half* base = Vc + (nd * 8 + g) * ASTR + ks * 16 + tg * 2;
                vf[nd][0] = *(const unsigned*)base;
                vf[nd][1] = *(const unsigned*)(base + 8);
            }
#pragma unroll
            for (int nd = 0; nd < 8; nd++)
                mma16816(O[nd], pf[ks], vf[nd]);
        }

        if (jt + 1 < jtN) {
            CP_WAIT0();
            __syncthreads();
        }
    }

    l_a += __shfl_xor_sync(0xffffffffu, l_a, 1);
    l_a += __shfl_xor_sync(0xffffffffu, l_a, 2);
    l_b += __shfl_xor_sync(0xffffffffu, l_b, 1);
    l_b += __shfl_xor_sync(0xffffffffu, l_b, 2);
    const float inv_a = 1.f / l_a;
    const float inv_b = 1.f / l_b;

    __half* Cb = g_ctx16 + (size_t)b * MB + h * DHEAD;
#pragma unroll
    for (int nd = 0; nd < 8; nd++) {
        const int c = nd * 8 + tg * 2;
        *(__half2*)(Cb + (size_t)row_a * HIDN + c) =
            __floats2half2_rn(O[nd][0] * inv_a, O[nd][1] * inv_a);
        *(__half2*)(Cb + (size_t)row_b * HIDN + c) =
            __floats2half2_rn(O[nd][2] * inv_b, O[nd][3] * inv_b);
    }
}

// ---------------------------------------------------------------------------
// Launcher
// ---------------------------------------------------------------------------
extern "C" void kernel_launch(void* const* d_in, const int* in_sizes, int n_in,
                              void* d_out, int out_size) {
    const float* key    = (const float*)d_in[0];
    const float* query  = (const float*)d_in[1];
    const float* value  = (const float*)d_in[2];
    const int*   seqlen = (const int*)  d_in[3];
    const float* pe     = (const float*)d_in[4];
    const float* Wk = (const float*)d_in[5],  *bk = (const float*)d_in[6];
    const float* Wq = (const float*)d_in[7],  *bq = (const float*)d_in[8];
    const float* Wv = (const float*)d_in[9],  *bv = (const float*)d_in[10];
    const float* Wr = (const float*)d_in[11], *br = (const float*)d_in[12];
    const float* u_bias = (const float*)d_in[13];
    const float* v_bias = (const float*)d_in[14];
    const float* Wf = (const float*)d_in[15], *bf = (const float*)d_in[16];
    float* out = (float*)d_out;

    __half *xk, *xq, *xv, *pe16, *wq16, *wk16, *wv16, *wr16, *wf16;
    __half *qu, *qv, *k16, *r16, *ctx16;
    cudaGetSymbolAddress((void**)&xk,   g_xk);
    cudaGetSymbolAddress((void**)&xq,   g_xq);
    cudaGetSymbolAddress((void**)&xv,   g_xv);
    cudaGetSymbolAddress((void**)&pe16, g_pe16);
    cudaGetSymbolAddress((void**)&wq16, g_wq16);
    cudaGetSymbolAddress((void**)&wk16, g_wk16);
    cudaGetSymbolAddress((void**)&wv16, g_wv16);
    cudaGetSymbolAddress((void**)&wr16, g_wr16);
    cudaGetSymbolAddress((void**)&wf16, g_wf16);
    cudaGetSymbolAddress((void**)&qu,   g_qu);
    cudaGetSymbolAddress((void**)&qv,   g_qv);
    cudaGetSymbolAddress((void**)&k16,  g_k16);
    cudaGetSymbolAddress((void**)&r16,  g_r16);
    cudaGetSymbolAddress((void**)&ctx16,g_ctx16);

    const int dynBytes = (64 * RSTR + 6 * 64 * ASTR) * (int)sizeof(__half);
    cudaFuncSetAttribute(flasha_kernel, cudaFuncAttributeMaxDynamicSharedMemorySize, dynBytes);
    const int finBytes = 6 * 64 * FSTR * (int)sizeof(__half);
    cudaFuncSetAttribute(final_kernel, cudaFuncAttributeMaxDynamicSharedMemorySize, finBytes);

    // 1. convert everything to fp16 (flattened)
    CvtArgs ca;
    ca.src[0] = key;   ca.dst[0] = xk;
    ca.src[1] = query; ca.dst[1] = xq;
    ca.src[2] = value; ca.dst[2] = xv;
    ca.src[3] = pe;    ca.dst[3] = pe16;
    ca.src[4] = Wq;    ca.dst[4] = wq16;
    ca.src[5] = Wk;    ca.dst[5] = wk16;
    ca.src[6] = Wv;    ca.dst[6] = wv16;
    ca.src[7] = Wr;    ca.dst[7] = wr16;
    ca.src[8] = Wf;    ca.dst[8] = wf16;
    {
        const int sizes[9] = {BB*LLEN*HIDN, BB*LLEN*HIDN, BB*LLEN*HIDN,
                              PROWS*HIDN, HIDN*HIDN, HIDN*HIDN, HIDN*HIDN,
                              HIDN*HIDN, HIDN*HIDN};
        int c = 0;
        for (int i = 0; i < 9; i++) { ca.cum[i] = c; c += sizes[i]; }
        ca.cum[9] = c;
        const int nblk = (c / 8 + 255) / 256;
        cvt_kernel<<<nblk, 256>>>(ca);
    }

    // 2. merged projections: Q (dual), K, V (transposed epilogue), R
    ProjArgs pj;
    pj.A[0] = xq;   pj.B[0] = wq16; pj.C0[0] = qu;  pj.C1[0] = qv;
    pj.bias[0] = bq; pj.mtiles[0] = 24; pj.epi[0] = 0;
    pj.A[1] = xk;   pj.B[1] = wk16; pj.C0[1] = k16; pj.C1[1] = nullptr;
    pj.bias[1] = bk; pj.mtiles[1] = 24; pj.epi[1] = 1;
    pj.A[2] = xv;   pj.B[2] = wv16; pj.C0[2] = nullptr; pj.C1[2] = nullptr;
    pj.bias[2] = bv; pj.mtiles[2] = 24; pj.epi[2] = 3;
    pj.A[3] = pe16; pj.B[3] = wr16; pj.C0[3] = r16; pj.C1[3] = nullptr;
    pj.bias[3] = br; pj.mtiles[3] = 6;  pj.epi[3] = 1;
    pj.ub = u_bias; pj.vb = v_bias;
    proj_kernel<<<dim3(HIDN / BN, 24, 4), 256>>>(pj);

    // 3. fused flash attention (seq_len tile skipping) -> ctx16
    flasha_kernel<<<dim3(LLEN / 64, NBH), 128, dynBytes>>>(seqlen);

    // 4. final projection (BK=64 pipeline) -> fp32 out
    final_kernel<<<dim3(HIDN / 64, (BB * LLEN) / 64), 256, finBytes>>>(ctx16, wf16, bf, out);
}